// round 1
// baseline (speedup 1.0000x reference)
#include <cuda_runtime.h>

#define NN 50000
#define NE 600000
#define LAT 128
#define NF 7
#define AP 132   // A-tile smem pitch (132 % 32 = 4 -> conflict-free dual-broadcast reads)

// ---------------- scratch (device globals: allocation-free rule) ----------------
__device__ float g_h[NN * LAT];
__device__ float g_t[NN * LAT];
__device__ float g_x[NN * LAT];
__device__ float g_agg[NN * LAT];
__device__ float g_degs[NN];
__device__ float g_degr[NN];
__device__ float g_invs[NN];
__device__ float g_invr[NN];

// ---------------- small kernels ----------------
__global__ void zero_deg_kernel() {
    int i = blockIdx.x * blockDim.x + threadIdx.x;
    if (i < NN) { g_degs[i] = 0.f; g_degr[i] = 0.f; }
}

__global__ void deg_kernel(const int* __restrict__ s, const int* __restrict__ r) {
    int e = blockIdx.x * blockDim.x + threadIdx.x;
    if (e < NE) {
        atomicAdd(&g_degs[s[e]], 1.f);
        atomicAdd(&g_degr[r[e]], 1.f);
    }
}

__global__ void invsqrt_kernel() {
    int i = blockIdx.x * blockDim.x + threadIdx.x;
    if (i < NN) {
        g_invs[i] = rsqrtf(fmaxf(g_degs[i], 1.f));
        g_invr[i] = rsqrtf(fmaxf(g_degr[i], 1.f));
    }
}

__global__ void embed_kernel(const float* __restrict__ nodes,
                             const float* __restrict__ We,
                             const float* __restrict__ be) {
    int idx = blockIdx.x * blockDim.x + threadIdx.x;
    if (idx >= NN * LAT) return;
    int n = idx >> 7, j = idx & 127;
    float acc = be[j];
#pragma unroll
    for (int k = 0; k < NF; k++)
        acc = fmaf(__ldg(&nodes[n * NF + k]), We[k * LAT + j], acc);
    g_h[idx] = acc;
}

__global__ void zero_agg_kernel() {
    int i = blockIdx.x * blockDim.x + threadIdx.x;  // float4 index
    if (i < NN * LAT / 4)
        ((float4*)g_agg)[i] = make_float4(0.f, 0.f, 0.f, 0.f);
}

// ---------------- GEMM: C[n][j] = relu(A[n][:] @ W + b) * (SCALE ? sc[n] : 1) ----------------
// block: 256 threads, tile 64 rows x 128 cols, thread micro-tile 4x8.
template <bool SCALE>
__global__ void __launch_bounds__(256, 2)
gemm_kernel(const float* __restrict__ A, const float* __restrict__ Wg,
            const float* __restrict__ bg, const float* __restrict__ sc,
            float* __restrict__ C) {
    extern __shared__ float sm[];
    float* Ws = sm;                 // [128][128]
    float* As = sm + LAT * LAT;     // [64][AP]
    int tid = threadIdx.x;

    // load full weight matrix (16384 floats = 4096 float4)
    {
        const float4* src = (const float4*)Wg;
        float4* dst = (float4*)Ws;
#pragma unroll
        for (int i = 0; i < 16; i++) dst[tid + 256 * i] = src[tid + 256 * i];
    }

    int ty = tid >> 4;   // 0..15
    int tx = tid & 15;   // 0..15
    int row0 = blockIdx.x * 64;

    __syncthreads();

    // load A tile 64x128 (2048 float4), zero-fill past NN
#pragma unroll
    for (int i = 0; i < 8; i++) {
        int f = tid + 256 * i;
        int rr = f >> 5, k4 = f & 31;
        int grow = row0 + rr;
        float4 v = make_float4(0.f, 0.f, 0.f, 0.f);
        if (grow < NN) v = ((const float4*)A)[grow * 32 + k4];
        *(float4*)(As + rr * AP + k4 * 4) = v;
    }
    __syncthreads();

    float acc[4][8];
#pragma unroll
    for (int i = 0; i < 4; i++)
#pragma unroll
        for (int j = 0; j < 8; j++) acc[i][j] = 0.f;

    const int r0 = ty * 4;
    const int c0 = tx * 8;

#pragma unroll 4
    for (int k = 0; k < LAT; k++) {
        float a[4];
#pragma unroll
        for (int i = 0; i < 4; i++) a[i] = As[(r0 + i) * AP + k];
        float4 wA = *(const float4*)(Ws + k * LAT + c0);
        float4 wB = *(const float4*)(Ws + k * LAT + c0 + 4);
        float w[8] = {wA.x, wA.y, wA.z, wA.w, wB.x, wB.y, wB.z, wB.w};
#pragma unroll
        for (int i = 0; i < 4; i++)
#pragma unroll
            for (int j = 0; j < 8; j++)
                acc[i][j] = fmaf(a[i], w[j], acc[i][j]);
    }

    float b[8];
#pragma unroll
    for (int j = 0; j < 8; j++) b[j] = bg[c0 + j];

#pragma unroll
    for (int i = 0; i < 4; i++) {
        int grow = row0 + r0 + i;
        if (grow < NN) {
            float s = SCALE ? sc[grow] : 1.f;
            float4 o1, o2;
            o1.x = fmaxf(acc[i][0] + b[0], 0.f) * s;
            o1.y = fmaxf(acc[i][1] + b[1], 0.f) * s;
            o1.z = fmaxf(acc[i][2] + b[2], 0.f) * s;
            o1.w = fmaxf(acc[i][3] + b[3], 0.f) * s;
            o2.x = fmaxf(acc[i][4] + b[4], 0.f) * s;
            o2.y = fmaxf(acc[i][5] + b[5], 0.f) * s;
            o2.z = fmaxf(acc[i][6] + b[6], 0.f) * s;
            o2.w = fmaxf(acc[i][7] + b[7], 0.f) * s;
            ((float4*)C)[grow * 32 + (c0 >> 2)] = o1;
            ((float4*)C)[grow * 32 + (c0 >> 2) + 1] = o2;
        }
    }
}

// ---------------- scatter: agg[recv] += x[send], one warp per edge, red.v4 ----------------
__global__ void scatter_kernel(const int* __restrict__ snd, const int* __restrict__ rcv) {
    int t = blockIdx.x * blockDim.x + threadIdx.x;
    int e = t >> 5;
    if (e >= NE) return;
    int q = t & 31;
    int s = snd[e], r = rcv[e];
    float4 v = ((const float4*)g_x)[s * 32 + q];
    float4* dst = &((float4*)g_agg)[r * 32 + q];
    asm volatile("red.global.add.v4.f32 [%0], {%1, %2, %3, %4};" ::"l"(dst),
                 "f"(v.x), "f"(v.y), "f"(v.z), "f"(v.w)
                 : "memory");
}

// ---------------- fused skip + inv_sqrt_r + layernorm (in-place on g_h) ----------------
__global__ void ln_kernel(const float* __restrict__ lns, const float* __restrict__ lnb) {
    int n = blockIdx.x;
    int j = threadIdx.x;  // 128
    float v = g_h[n * LAT + j] + g_agg[n * LAT + j] * g_invr[n];
    float s1 = v, s2 = v * v;
#pragma unroll
    for (int o = 16; o; o >>= 1) {
        s1 += __shfl_xor_sync(0xFFFFFFFFu, s1, o);
        s2 += __shfl_xor_sync(0xFFFFFFFFu, s2, o);
    }
    __shared__ float sh1[4], sh2[4];
    if ((j & 31) == 0) { sh1[j >> 5] = s1; sh2[j >> 5] = s2; }
    __syncthreads();
    float m1 = (sh1[0] + sh1[1] + sh1[2] + sh1[3]) * (1.f / 128.f);
    float m2 = (sh2[0] + sh2[1] + sh2[2] + sh2[3]) * (1.f / 128.f);
    float var = m2 - m1 * m1;
    g_h[n * LAT + j] = (v - m1) * rsqrtf(var + 1e-6f) * lns[j] + lnb[j];
}

// ---------------- decoder: out = h @ W_dec + b_dec, one warp per node ----------------
__global__ void dec_kernel(const float* __restrict__ Wd, const float* __restrict__ bd,
                           float* __restrict__ out) {
    __shared__ float Wds[LAT * NF];
    int tid = threadIdx.x;  // 256
    for (int i = tid; i < LAT * NF; i += 256) Wds[i] = Wd[i];
    __syncthreads();
    int warp = tid >> 5, lane = tid & 31;
    int n = blockIdx.x * 8 + warp;
    if (n >= NN) return;
    float4 hv = ((const float4*)g_h)[n * 32 + lane];
#pragma unroll
    for (int f = 0; f < NF; f++) {
        float p = hv.x * Wds[(lane * 4 + 0) * NF + f] +
                  hv.y * Wds[(lane * 4 + 1) * NF + f] +
                  hv.z * Wds[(lane * 4 + 2) * NF + f] +
                  hv.w * Wds[(lane * 4 + 3) * NF + f];
#pragma unroll
        for (int o = 16; o; o >>= 1) p += __shfl_xor_sync(0xFFFFFFFFu, p, o);
        if (lane == 0) out[n * NF + f] = p + bd[f];
    }
}

// ---------------- launch ----------------
extern "C" void kernel_launch(void* const* d_in, const int* in_sizes, int n_in,
                              void* d_out, int out_size) {
    const float* nodes    = (const float*)d_in[0];
    const int*   senders  = (const int*)d_in[1];
    const int*   receivers= (const int*)d_in[2];
    const float* W_embed  = (const float*)d_in[3];
    const float* b_embed  = (const float*)d_in[4];
    const float* mlp_W    = (const float*)d_in[5];  // [3][2][128][128]
    const float* mlp_b    = (const float*)d_in[6];  // [3][2][128]
    const float* ln_scale = (const float*)d_in[7];  // [3][128]
    const float* ln_bias  = (const float*)d_in[8];  // [3][128]
    const float* W_dec    = (const float*)d_in[9];  // [128][7]
    const float* b_dec    = (const float*)d_in[10]; // [7]
    float* out = (float*)d_out;

    const int SMEM_BYTES = (LAT * LAT + 64 * AP) * (int)sizeof(float);  // 99328
    cudaFuncSetAttribute((const void*)gemm_kernel<false>,
                         cudaFuncAttributeMaxDynamicSharedMemorySize, SMEM_BYTES);
    cudaFuncSetAttribute((const void*)gemm_kernel<true>,
                         cudaFuncAttributeMaxDynamicSharedMemorySize, SMEM_BYTES);

    float *p_h, *p_t, *p_x, *p_invs;
    cudaGetSymbolAddress((void**)&p_h, g_h);
    cudaGetSymbolAddress((void**)&p_t, g_t);
    cudaGetSymbolAddress((void**)&p_x, g_x);
    cudaGetSymbolAddress((void**)&p_invs, g_invs);

    zero_deg_kernel<<<(NN + 255) / 256, 256>>>();
    deg_kernel<<<(NE + 255) / 256, 256>>>(senders, receivers);
    invsqrt_kernel<<<(NN + 255) / 256, 256>>>();
    embed_kernel<<<(NN * LAT + 255) / 256, 256>>>(nodes, W_embed, b_embed);

    const int gemm_grid = (NN + 63) / 64;  // 782
    for (int s = 0; s < 3; s++) {
        const float* W1 = mlp_W + (size_t)(s * 2 + 0) * LAT * LAT;
        const float* W2 = mlp_W + (size_t)(s * 2 + 1) * LAT * LAT;
        const float* b1 = mlp_b + (size_t)(s * 2 + 0) * LAT;
        const float* b2 = mlp_b + (size_t)(s * 2 + 1) * LAT;

        gemm_kernel<false><<<gemm_grid, 256, SMEM_BYTES>>>(p_h, W1, b1, nullptr, p_t);
        gemm_kernel<true><<<gemm_grid, 256, SMEM_BYTES>>>(p_t, W2, b2, p_invs, p_x);

        zero_agg_kernel<<<(NN * LAT / 4 + 255) / 256, 256>>>();
        scatter_kernel<<<(NE * 32 + 255) / 256, 256>>>(senders, receivers);
        ln_kernel<<<NN, 128>>>(ln_scale + s * LAT, ln_bias + s * LAT);
    }

    dec_kernel<<<(NN + 7) / 8, 256>>>(W_dec, b_dec, out);
}

// round 2
// speedup vs baseline: 1.2409x; 1.2409x over previous
#include <cuda_runtime.h>

#define NN 50000
#define NE 600000
#define LAT 128
#define NF 7
#define AP 132   // A-tile smem pitch

// ---------------- scratch (device globals: allocation-free rule) ----------------
__device__ float g_h[NN * LAT];
__device__ float g_t[NN * LAT];
__device__ float g_x[NN * LAT];
__device__ float g_degs[NN];
__device__ float g_degr[NN];
__device__ float g_invs[NN];
__device__ float g_invr[NN];
__device__ int   g_off[NN + 1];
__device__ int   g_cursor[NN];
__device__ int   g_esrc[NE];

// ---------------- f32x2 helpers (sm_103a packed fp32) ----------------
__device__ __forceinline__ unsigned long long splat2(float a) {
    unsigned long long r;
    asm("mov.b64 %0, {%1, %1};" : "=l"(r) : "f"(a));
    return r;
}
__device__ __forceinline__ void fma2(unsigned long long& d, unsigned long long a,
                                     unsigned long long b) {
    asm("fma.rn.f32x2 %0, %1, %2, %0;" : "+l"(d) : "l"(a), "l"(b));
}
__device__ __forceinline__ void unpack2(unsigned long long v, float& lo, float& hi) {
    asm("mov.b64 {%0, %1}, %2;" : "=f"(lo), "=f"(hi) : "l"(v));
}

// ---------------- small kernels ----------------
__global__ void zero_deg_kernel() {
    int i = blockIdx.x * blockDim.x + threadIdx.x;
    if (i < NN) { g_degs[i] = 0.f; g_degr[i] = 0.f; }
}

__global__ void deg_kernel(const int* __restrict__ s, const int* __restrict__ r) {
    int e = blockIdx.x * blockDim.x + threadIdx.x;
    if (e < NE) {
        atomicAdd(&g_degs[s[e]], 1.f);
        atomicAdd(&g_degr[r[e]], 1.f);
    }
}

__global__ void invsqrt_kernel() {
    int i = blockIdx.x * blockDim.x + threadIdx.x;
    if (i < NN) {
        g_invs[i] = rsqrtf(fmaxf(g_degs[i], 1.f));
        g_invr[i] = rsqrtf(fmaxf(g_degr[i], 1.f));
    }
}

// exclusive scan of (int)g_degr -> g_off, g_cursor. One block of 1024 threads.
__global__ void scan_kernel() {
    __shared__ int ssum[1024];
    const int C = (NN + 1023) / 1024;  // 49
    int t = threadIdx.x;
    int base = t * C;
    int sum = 0;
    for (int i = 0; i < C; i++) {
        int idx = base + i;
        if (idx < NN) sum += (int)g_degr[idx];
    }
    ssum[t] = sum;
    __syncthreads();
    for (int o = 1; o < 1024; o <<= 1) {
        int v = (t >= o) ? ssum[t - o] : 0;
        __syncthreads();
        ssum[t] += v;
        __syncthreads();
    }
    int run = ssum[t] - sum;  // exclusive prefix for this chunk
    for (int i = 0; i < C; i++) {
        int idx = base + i;
        if (idx < NN) {
            g_off[idx] = run;
            g_cursor[idx] = run;
            run += (int)g_degr[idx];
        }
    }
    if (t == 1023) g_off[NN] = NE;
}

__global__ void place_kernel(const int* __restrict__ snd, const int* __restrict__ rcv) {
    int e = blockIdx.x * blockDim.x + threadIdx.x;
    if (e < NE) {
        int pos = atomicAdd(&g_cursor[rcv[e]], 1);
        g_esrc[pos] = snd[e];
    }
}

// ---------------- embed: warp per node ----------------
__global__ void embed_kernel(const float* __restrict__ nodes,
                             const float* __restrict__ We,
                             const float* __restrict__ be) {
    __shared__ float Wsh[NF * LAT];
    __shared__ float bsh[LAT];
    int tid = threadIdx.x;
    for (int i = tid; i < NF * LAT; i += 256) Wsh[i] = We[i];
    if (tid < LAT) bsh[tid] = be[tid];
    __syncthreads();
    int warp = tid >> 5, lane = tid & 31;
    int n = blockIdx.x * 8 + warp;
    if (n >= NN) return;
    float t = (lane < NF) ? nodes[n * NF + lane] : 0.f;
    float f[NF];
#pragma unroll
    for (int k = 0; k < NF; k++) f[k] = __shfl_sync(0xFFFFFFFFu, t, k);
    int c0 = lane * 4;
    float4 o = make_float4(bsh[c0], bsh[c0 + 1], bsh[c0 + 2], bsh[c0 + 3]);
#pragma unroll
    for (int k = 0; k < NF; k++) {
        float4 w = *(const float4*)(Wsh + k * LAT + c0);
        o.x = fmaf(f[k], w.x, o.x);
        o.y = fmaf(f[k], w.y, o.y);
        o.z = fmaf(f[k], w.z, o.z);
        o.w = fmaf(f[k], w.w, o.w);
    }
    ((float4*)g_h)[n * 32 + lane] = o;
}

// ---------------- GEMM: C = relu(A @ W + b) * (SCALE ? sc : 1), f32x2 mainloop ----------------
template <bool SCALE>
__global__ void __launch_bounds__(256, 2)
gemm_kernel(const float* __restrict__ A, const float* __restrict__ Wg,
            const float* __restrict__ bg, const float* __restrict__ sc,
            float* __restrict__ C) {
    extern __shared__ float sm[];
    float* Ws = sm;                 // [128][128]
    float* As = sm + LAT * LAT;     // [64][AP]
    int tid = threadIdx.x;

    {
        const float4* src = (const float4*)Wg;
        float4* dst = (float4*)Ws;
#pragma unroll
        for (int i = 0; i < 16; i++) dst[tid + 256 * i] = src[tid + 256 * i];
    }

    int ty = tid >> 4;   // 0..15
    int tx = tid & 15;   // 0..15
    int row0 = blockIdx.x * 64;

    __syncthreads();

#pragma unroll
    for (int i = 0; i < 8; i++) {
        int f = tid + 256 * i;
        int rr = f >> 5, k4 = f & 31;
        int grow = row0 + rr;
        float4 v = make_float4(0.f, 0.f, 0.f, 0.f);
        if (grow < NN) v = ((const float4*)A)[grow * 32 + k4];
        *(float4*)(As + rr * AP + k4 * 4) = v;
    }
    __syncthreads();

    unsigned long long acc[4][4];
#pragma unroll
    for (int i = 0; i < 4; i++)
#pragma unroll
        for (int j = 0; j < 4; j++) acc[i][j] = 0ull;

    const int r0 = ty * 4;
    const int c0 = tx * 8;

#pragma unroll 4
    for (int k = 0; k < LAT; k++) {
        unsigned long long a2[4];
#pragma unroll
        for (int i = 0; i < 4; i++) a2[i] = splat2(As[(r0 + i) * AP + k]);
        const unsigned long long* wp = (const unsigned long long*)(Ws + k * LAT + c0);
        unsigned long long w0 = wp[0], w1 = wp[1], w2 = wp[2], w3 = wp[3];
#pragma unroll
        for (int i = 0; i < 4; i++) {
            fma2(acc[i][0], a2[i], w0);
            fma2(acc[i][1], a2[i], w1);
            fma2(acc[i][2], a2[i], w2);
            fma2(acc[i][3], a2[i], w3);
        }
    }

    float b[8];
#pragma unroll
    for (int j = 0; j < 8; j++) b[j] = bg[c0 + j];

#pragma unroll
    for (int i = 0; i < 4; i++) {
        int grow = row0 + r0 + i;
        if (grow < NN) {
            float o[8];
#pragma unroll
            for (int j = 0; j < 4; j++) unpack2(acc[i][j], o[2 * j], o[2 * j + 1]);
            float s = SCALE ? sc[grow] : 1.f;
            float4 o1, o2;
            o1.x = fmaxf(o[0] + b[0], 0.f) * s;
            o1.y = fmaxf(o[1] + b[1], 0.f) * s;
            o1.z = fmaxf(o[2] + b[2], 0.f) * s;
            o1.w = fmaxf(o[3] + b[3], 0.f) * s;
            o2.x = fmaxf(o[4] + b[4], 0.f) * s;
            o2.y = fmaxf(o[5] + b[5], 0.f) * s;
            o2.z = fmaxf(o[6] + b[6], 0.f) * s;
            o2.w = fmaxf(o[7] + b[7], 0.f) * s;
            ((float4*)C)[grow * 32 + (c0 >> 2)] = o1;
            ((float4*)C)[grow * 32 + (c0 >> 2) + 1] = o2;
        }
    }
}

// ---------------- fused CSR-gather + skip + inv_sqrt_r + layernorm ----------------
__global__ void gather_ln_kernel(const float* __restrict__ lns,
                                 const float* __restrict__ lnb) {
    int gw = (blockIdx.x * blockDim.x + threadIdx.x) >> 5;
    if (gw >= NN) return;
    int lane = threadIdx.x & 31;
    int n = gw;
    int beg = g_off[n], end = g_off[n + 1];

    const float4* X = (const float4*)g_x;
    float4 acc = make_float4(0.f, 0.f, 0.f, 0.f);
    int i = beg;
    for (; i + 3 < end; i += 4) {
        int s0 = g_esrc[i], s1 = g_esrc[i + 1], s2 = g_esrc[i + 2], s3 = g_esrc[i + 3];
        float4 v0 = __ldg(&X[s0 * 32 + lane]);
        float4 v1 = __ldg(&X[s1 * 32 + lane]);
        float4 v2 = __ldg(&X[s2 * 32 + lane]);
        float4 v3 = __ldg(&X[s3 * 32 + lane]);
        acc.x += v0.x + v1.x + v2.x + v3.x;
        acc.y += v0.y + v1.y + v2.y + v3.y;
        acc.z += v0.z + v1.z + v2.z + v3.z;
        acc.w += v0.w + v1.w + v2.w + v3.w;
    }
    for (; i < end; i++) {
        int s = g_esrc[i];
        float4 v = __ldg(&X[s * 32 + lane]);
        acc.x += v.x; acc.y += v.y; acc.z += v.z; acc.w += v.w;
    }

    float ir = g_invr[n];
    float4 h4 = ((const float4*)g_h)[n * 32 + lane];
    float4 v;
    v.x = h4.x + acc.x * ir;
    v.y = h4.y + acc.y * ir;
    v.z = h4.z + acc.z * ir;
    v.w = h4.w + acc.w * ir;

    float s1 = v.x + v.y + v.z + v.w;
    float s2 = v.x * v.x + v.y * v.y + v.z * v.z + v.w * v.w;
#pragma unroll
    for (int o = 16; o; o >>= 1) {
        s1 += __shfl_xor_sync(0xFFFFFFFFu, s1, o);
        s2 += __shfl_xor_sync(0xFFFFFFFFu, s2, o);
    }
    float mean = s1 * (1.f / 128.f);
    float var = s2 * (1.f / 128.f) - mean * mean;
    float rs = rsqrtf(var + 1e-6f);

    float4 g4 = __ldg(&((const float4*)lns)[lane]);
    float4 b4 = __ldg(&((const float4*)lnb)[lane]);
    float4 o;
    o.x = (v.x - mean) * rs * g4.x + b4.x;
    o.y = (v.y - mean) * rs * g4.y + b4.y;
    o.z = (v.z - mean) * rs * g4.z + b4.z;
    o.w = (v.w - mean) * rs * g4.w + b4.w;
    ((float4*)g_h)[n * 32 + lane] = o;
}

// ---------------- decoder: out = h @ W_dec + b_dec, one warp per node ----------------
__global__ void dec_kernel(const float* __restrict__ Wd, const float* __restrict__ bd,
                           float* __restrict__ out) {
    __shared__ float Wds[LAT * NF];
    int tid = threadIdx.x;
    for (int i = tid; i < LAT * NF; i += 256) Wds[i] = Wd[i];
    __syncthreads();
    int warp = tid >> 5, lane = tid & 31;
    int n = blockIdx.x * 8 + warp;
    if (n >= NN) return;
    float4 hv = ((const float4*)g_h)[n * 32 + lane];
#pragma unroll
    for (int f = 0; f < NF; f++) {
        float p = hv.x * Wds[(lane * 4 + 0) * NF + f] +
                  hv.y * Wds[(lane * 4 + 1) * NF + f] +
                  hv.z * Wds[(lane * 4 + 2) * NF + f] +
                  hv.w * Wds[(lane * 4 + 3) * NF + f];
#pragma unroll
        for (int o = 16; o; o >>= 1) p += __shfl_xor_sync(0xFFFFFFFFu, p, o);
        if (lane == 0) out[n * NF + f] = p + bd[f];
    }
}

// ---------------- launch ----------------
extern "C" void kernel_launch(void* const* d_in, const int* in_sizes, int n_in,
                              void* d_out, int out_size) {
    const float* nodes    = (const float*)d_in[0];
    const int*   senders  = (const int*)d_in[1];
    const int*   receivers= (const int*)d_in[2];
    const float* W_embed  = (const float*)d_in[3];
    const float* b_embed  = (const float*)d_in[4];
    const float* mlp_W    = (const float*)d_in[5];
    const float* mlp_b    = (const float*)d_in[6];
    const float* ln_scale = (const float*)d_in[7];
    const float* ln_bias  = (const float*)d_in[8];
    const float* W_dec    = (const float*)d_in[9];
    const float* b_dec    = (const float*)d_in[10];
    float* out = (float*)d_out;

    const int SMEM_BYTES = (LAT * LAT + 64 * AP) * (int)sizeof(float);  // 99328
    cudaFuncSetAttribute((const void*)gemm_kernel<false>,
                         cudaFuncAttributeMaxDynamicSharedMemorySize, SMEM_BYTES);
    cudaFuncSetAttribute((const void*)gemm_kernel<true>,
                         cudaFuncAttributeMaxDynamicSharedMemorySize, SMEM_BYTES);

    float *p_h, *p_t, *p_x, *p_invs;
    cudaGetSymbolAddress((void**)&p_h, g_h);
    cudaGetSymbolAddress((void**)&p_t, g_t);
    cudaGetSymbolAddress((void**)&p_x, g_x);
    cudaGetSymbolAddress((void**)&p_invs, g_invs);

    const int gemm_grid = (NN + 63) / 64;

    // launch order chosen so ncu (-s 5 -c 1) captures the first GEMM
    zero_deg_kernel<<<(NN + 255) / 256, 256>>>();                         // 1
    deg_kernel<<<(NE + 255) / 256, 256>>>(senders, receivers);            // 2
    embed_kernel<<<(NN + 7) / 8, 256>>>(nodes, W_embed, b_embed);         // 3
    invsqrt_kernel<<<(NN + 255) / 256, 256>>>();                          // 4
    scan_kernel<<<1, 1024>>>();                                           // 5

    for (int s = 0; s < 3; s++) {
        const float* W1 = mlp_W + (size_t)(s * 2 + 0) * LAT * LAT;
        const float* W2 = mlp_W + (size_t)(s * 2 + 1) * LAT * LAT;
        const float* b1 = mlp_b + (size_t)(s * 2 + 0) * LAT;
        const float* b2 = mlp_b + (size_t)(s * 2 + 1) * LAT;

        gemm_kernel<false><<<gemm_grid, 256, SMEM_BYTES>>>(p_h, W1, b1, nullptr, p_t);  // 6 on s=0
        gemm_kernel<true><<<gemm_grid, 256, SMEM_BYTES>>>(p_t, W2, b2, p_invs, p_x);
        if (s == 0)
            place_kernel<<<(NE + 255) / 256, 256>>>(senders, receivers);
        gather_ln_kernel<<<(NN + 7) / 8, 256>>>(ln_scale + s * LAT, ln_bias + s * LAT);
    }

    dec_kernel<<<(NN + 7) / 8, 256>>>(W_dec, b_dec, out);
}

// round 3
// speedup vs baseline: 1.4887x; 1.1997x over previous
#include <cuda_runtime.h>

#define NN 50000
#define NE 600000
#define LAT 128
#define NF 7
#define AP 132   // A-tile smem pitch (conflict-free)

// ---------------- scratch (device globals: allocation-free rule) ----------------
__device__ float g_h[NN * LAT];
__device__ float g_x[NN * LAT];
__device__ float g_degs[NN];
__device__ float g_degr[NN];
__device__ float g_invs[NN];
__device__ float g_invr[NN];
__device__ int   g_off[NN + 1];
__device__ int   g_cursor[NN];
__device__ int   g_esrc[NE];
__device__ int   g_bsum[64];

// ---------------- f32x2 helpers ----------------
__device__ __forceinline__ unsigned long long splat2(float a) {
    unsigned long long r;
    asm("mov.b64 %0, {%1, %1};" : "=l"(r) : "f"(a));
    return r;
}
__device__ __forceinline__ void fma2(unsigned long long& d, unsigned long long a,
                                     unsigned long long b) {
    asm("fma.rn.f32x2 %0, %1, %2, %0;" : "+l"(d) : "l"(a), "l"(b));
}
__device__ __forceinline__ void unpack2(unsigned long long v, float& lo, float& hi) {
    asm("mov.b64 {%0, %1}, %2;" : "=f"(lo), "=f"(hi) : "l"(v));
}

// ---------------- embed (warp per node) + zero deg arrays ----------------
__global__ void embed_kernel(const float* __restrict__ nodes,
                             const float* __restrict__ We,
                             const float* __restrict__ be) {
    __shared__ float Wsh[NF * LAT];
    __shared__ float bsh[LAT];
    int tid = threadIdx.x;
    int gid = blockIdx.x * 256 + tid;
    if (gid < NN) { g_degs[gid] = 0.f; g_degr[gid] = 0.f; }
    for (int i = tid; i < NF * LAT; i += 256) Wsh[i] = We[i];
    if (tid < LAT) bsh[tid] = be[tid];
    __syncthreads();
    int warp = tid >> 5, lane = tid & 31;
    int n = blockIdx.x * 8 + warp;
    if (n >= NN) return;
    float t = (lane < NF) ? nodes[n * NF + lane] : 0.f;
    float f[NF];
#pragma unroll
    for (int k = 0; k < NF; k++) f[k] = __shfl_sync(0xFFFFFFFFu, t, k);
    int c0 = lane * 4;
    float4 o = make_float4(bsh[c0], bsh[c0 + 1], bsh[c0 + 2], bsh[c0 + 3]);
#pragma unroll
    for (int k = 0; k < NF; k++) {
        float4 w = *(const float4*)(Wsh + k * LAT + c0);
        o.x = fmaf(f[k], w.x, o.x);
        o.y = fmaf(f[k], w.y, o.y);
        o.z = fmaf(f[k], w.z, o.z);
        o.w = fmaf(f[k], w.w, o.w);
    }
    ((float4*)g_h)[n * 32 + lane] = o;
}

__global__ void deg_kernel(const int* __restrict__ s, const int* __restrict__ r) {
    int e = blockIdx.x * blockDim.x + threadIdx.x;
    if (e < NE) {
        atomicAdd(&g_degs[s[e]], 1.f);
        atomicAdd(&g_degr[r[e]], 1.f);
    }
}

// ---------------- scan phase 1: block sums of (int)degr + invsqrt ----------------
__global__ void scan1_kernel() {
    int i = blockIdx.x * 1024 + threadIdx.x;
    int v = 0;
    if (i < NN) {
        float ds = g_degs[i], dr = g_degr[i];
        g_invs[i] = rsqrtf(fmaxf(ds, 1.f));
        g_invr[i] = rsqrtf(fmaxf(dr, 1.f));
        v = (int)dr;
    }
#pragma unroll
    for (int o = 16; o; o >>= 1) v += __shfl_xor_sync(0xFFFFFFFFu, v, o);
    __shared__ int ws[32];
    int lane = threadIdx.x & 31, warp = threadIdx.x >> 5;
    if (lane == 0) ws[warp] = v;
    __syncthreads();
    if (warp == 0) {
        int t = ws[lane];
#pragma unroll
        for (int o = 16; o; o >>= 1) t += __shfl_xor_sync(0xFFFFFFFFu, t, o);
        if (lane == 0) g_bsum[blockIdx.x] = t;
    }
}

// ---------------- scan phase 2: exclusive scan of 49 block sums ----------------
__global__ void scan2_kernel(int nblocks) {
    // single warp, serial-free shuffle scan over <=64 entries
    int t = threadIdx.x;  // 64
    int v = (t < nblocks) ? g_bsum[t] : 0;
    int x = v;
#pragma unroll
    for (int o = 1; o < 32; o <<= 1) {
        int y = __shfl_up_sync(0xFFFFFFFFu, x, o);
        if ((t & 31) >= o) x += y;
    }
    __shared__ int w0sum;
    if (t == 31) w0sum = x;
    __syncthreads();
    if (t >= 32) x += w0sum;
    if (t < nblocks) g_bsum[t] = x - v;  // exclusive
}

// ---------------- scan phase 3: block-local scan + fixup -> g_off, g_cursor ----------------
__global__ void scan3_kernel() {
    int i = blockIdx.x * 1024 + threadIdx.x;
    int lane = threadIdx.x & 31, warp = threadIdx.x >> 5;
    int v = (i < NN) ? (int)g_degr[i] : 0;
    int x = v;
#pragma unroll
    for (int o = 1; o < 32; o <<= 1) {
        int y = __shfl_up_sync(0xFFFFFFFFu, x, o);
        if (lane >= o) x += y;
    }
    __shared__ int ws[32];
    if (lane == 31) ws[warp] = x;
    __syncthreads();
    if (warp == 0) {
        int t = ws[lane];
        int xx = t;
#pragma unroll
        for (int o = 1; o < 32; o <<= 1) {
            int y = __shfl_up_sync(0xFFFFFFFFu, xx, o);
            if (lane >= o) xx += y;
        }
        ws[lane] = xx - t;  // exclusive warp offsets
    }
    __syncthreads();
    int ex = x - v + ws[warp] + g_bsum[blockIdx.x];
    if (i < NN) { g_off[i] = ex; g_cursor[i] = ex; }
    if (i == 0) g_off[NN] = NE;
}

__global__ void place_kernel(const int* __restrict__ snd, const int* __restrict__ rcv) {
    int e = blockIdx.x * blockDim.x + threadIdx.x;
    if (e < NE) {
        int pos = atomicAdd(&g_cursor[rcv[e]], 1);
        g_esrc[pos] = snd[e];
    }
}

// ---------------- fused 2-layer MLP: x = relu(relu(h@W1+b1)@W2+b2) * invs ----------------
// 512 threads, tile 128 rows x 128 cols, micro-tile 4x8, intermediate kept in smem.
__global__ void __launch_bounds__(512, 1)
mlp_kernel(const float* __restrict__ A, const float* __restrict__ W1g,
           const float* __restrict__ W2g, const float* __restrict__ b1g,
           const float* __restrict__ b2g, const float* __restrict__ sc,
           float* __restrict__ C) {
    extern __shared__ float sm[];
    float* W1s = sm;                    // [128][128]
    float* W2s = sm + LAT * LAT;        // [128][128]
    float* As  = sm + 2 * LAT * LAT;    // [128][AP]
    int tid = threadIdx.x;
    int ty = tid >> 4;   // 0..31
    int tx = tid & 15;   // 0..15
    const int r0 = ty * 4;
    const int c0 = tx * 8;
    int row0 = blockIdx.x * 128;

    // load W1 and W2 (adjacent, 8192 float4)
    {
        float4* dst = (float4*)sm;
#pragma unroll
        for (int i = 0; i < 8; i++) dst[tid + 512 * i] = ((const float4*)W1g)[tid + 512 * i];
#pragma unroll
        for (int i = 0; i < 8; i++)
            dst[4096 + tid + 512 * i] = ((const float4*)W2g)[tid + 512 * i];
    }
    // load A tile 128x128 (4096 float4)
#pragma unroll
    for (int i = 0; i < 8; i++) {
        int f = tid + 512 * i;
        int rr = f >> 5, k4 = f & 31;
        int grow = row0 + rr;
        float4 v = make_float4(0.f, 0.f, 0.f, 0.f);
        if (grow < NN) v = ((const float4*)A)[grow * 32 + k4];
        *(float4*)(As + rr * AP + k4 * 4) = v;
    }

    float b1[8], b2[8];
#pragma unroll
    for (int j = 0; j < 8; j++) { b1[j] = b1g[c0 + j]; b2[j] = b2g[c0 + j]; }

    __syncthreads();

    unsigned long long acc[4][4];
#pragma unroll
    for (int i = 0; i < 4; i++)
#pragma unroll
        for (int j = 0; j < 4; j++) acc[i][j] = 0ull;

    // ---- layer 1 mainloop ----
#pragma unroll 4
    for (int k = 0; k < LAT; k++) {
        unsigned long long a2[4];
#pragma unroll
        for (int i = 0; i < 4; i++) a2[i] = splat2(As[(r0 + i) * AP + k]);
        const unsigned long long* wp = (const unsigned long long*)(W1s + k * LAT + c0);
        unsigned long long w0 = wp[0], w1 = wp[1], w2 = wp[2], w3 = wp[3];
#pragma unroll
        for (int i = 0; i < 4; i++) {
            fma2(acc[i][0], a2[i], w0);
            fma2(acc[i][1], a2[i], w1);
            fma2(acc[i][2], a2[i], w2);
            fma2(acc[i][3], a2[i], w3);
        }
    }

    __syncthreads();  // all reads of As done before overwrite

    // epilogue 1: relu + bias, write t back into As
#pragma unroll
    for (int i = 0; i < 4; i++) {
        float o[8];
#pragma unroll
        for (int j = 0; j < 4; j++) unpack2(acc[i][j], o[2 * j], o[2 * j + 1]);
        float4 t1, t2;
        t1.x = fmaxf(o[0] + b1[0], 0.f);
        t1.y = fmaxf(o[1] + b1[1], 0.f);
        t1.z = fmaxf(o[2] + b1[2], 0.f);
        t1.w = fmaxf(o[3] + b1[3], 0.f);
        t2.x = fmaxf(o[4] + b1[4], 0.f);
        t2.y = fmaxf(o[5] + b1[5], 0.f);
        t2.z = fmaxf(o[6] + b1[6], 0.f);
        t2.w = fmaxf(o[7] + b1[7], 0.f);
        *(float4*)(As + (r0 + i) * AP + c0) = t1;
        *(float4*)(As + (r0 + i) * AP + c0 + 4) = t2;
#pragma unroll
        for (int j = 0; j < 4; j++) acc[i][j] = 0ull;
    }

    __syncthreads();

    // ---- layer 2 mainloop ----
#pragma unroll 4
    for (int k = 0; k < LAT; k++) {
        unsigned long long a2[4];
#pragma unroll
        for (int i = 0; i < 4; i++) a2[i] = splat2(As[(r0 + i) * AP + k]);
        const unsigned long long* wp = (const unsigned long long*)(W2s + k * LAT + c0);
        unsigned long long w0 = wp[0], w1 = wp[1], w2 = wp[2], w3 = wp[3];
#pragma unroll
        for (int i = 0; i < 4; i++) {
            fma2(acc[i][0], a2[i], w0);
            fma2(acc[i][1], a2[i], w1);
            fma2(acc[i][2], a2[i], w2);
            fma2(acc[i][3], a2[i], w3);
        }
    }

    // epilogue 2: relu + bias, scale by invs, store
#pragma unroll
    for (int i = 0; i < 4; i++) {
        int grow = row0 + r0 + i;
        if (grow < NN) {
            float o[8];
#pragma unroll
            for (int j = 0; j < 4; j++) unpack2(acc[i][j], o[2 * j], o[2 * j + 1]);
            float s = sc[grow];
            float4 o1, o2;
            o1.x = fmaxf(o[0] + b2[0], 0.f) * s;
            o1.y = fmaxf(o[1] + b2[1], 0.f) * s;
            o1.z = fmaxf(o[2] + b2[2], 0.f) * s;
            o1.w = fmaxf(o[3] + b2[3], 0.f) * s;
            o2.x = fmaxf(o[4] + b2[4], 0.f) * s;
            o2.y = fmaxf(o[5] + b2[5], 0.f) * s;
            o2.z = fmaxf(o[6] + b2[6], 0.f) * s;
            o2.w = fmaxf(o[7] + b2[7], 0.f) * s;
            ((float4*)C)[grow * 32 + (c0 >> 2)] = o1;
            ((float4*)C)[grow * 32 + (c0 >> 2) + 1] = o2;
        }
    }
}

// ---------------- fused CSR-gather + skip + inv_sqrt_r + layernorm ----------------
__global__ void gather_ln_kernel(const float* __restrict__ lns,
                                 const float* __restrict__ lnb) {
    int gw = (blockIdx.x * blockDim.x + threadIdx.x) >> 5;
    if (gw >= NN) return;
    int lane = threadIdx.x & 31;
    int n = gw;
    int beg = g_off[n], end = g_off[n + 1];

    const float4* X = (const float4*)g_x;
    float4 acc = make_float4(0.f, 0.f, 0.f, 0.f);
    int i = beg;
    for (; i + 3 < end; i += 4) {
        int s0 = g_esrc[i], s1 = g_esrc[i + 1], s2 = g_esrc[i + 2], s3 = g_esrc[i + 3];
        float4 v0 = __ldg(&X[s0 * 32 + lane]);
        float4 v1 = __ldg(&X[s1 * 32 + lane]);
        float4 v2 = __ldg(&X[s2 * 32 + lane]);
        float4 v3 = __ldg(&X[s3 * 32 + lane]);
        acc.x += v0.x + v1.x + v2.x + v3.x;
        acc.y += v0.y + v1.y + v2.y + v3.y;
        acc.z += v0.z + v1.z + v2.z + v3.z;
        acc.w += v0.w + v1.w + v2.w + v3.w;
    }
    for (; i < end; i++) {
        int s = g_esrc[i];
        float4 v = __ldg(&X[s * 32 + lane]);
        acc.x += v.x; acc.y += v.y; acc.z += v.z; acc.w += v.w;
    }

    float ir = g_invr[n];
    float4 h4 = ((const float4*)g_h)[n * 32 + lane];
    float4 v;
    v.x = h4.x + acc.x * ir;
    v.y = h4.y + acc.y * ir;
    v.z = h4.z + acc.z * ir;
    v.w = h4.w + acc.w * ir;

    float s1 = v.x + v.y + v.z + v.w;
    float s2 = v.x * v.x + v.y * v.y + v.z * v.z + v.w * v.w;
#pragma unroll
    for (int o = 16; o; o >>= 1) {
        s1 += __shfl_xor_sync(0xFFFFFFFFu, s1, o);
        s2 += __shfl_xor_sync(0xFFFFFFFFu, s2, o);
    }
    float mean = s1 * (1.f / 128.f);
    float var = s2 * (1.f / 128.f) - mean * mean;
    float rs = rsqrtf(var + 1e-6f);

    float4 g4 = __ldg(&((const float4*)lns)[lane]);
    float4 b4 = __ldg(&((const float4*)lnb)[lane]);
    float4 o;
    o.x = (v.x - mean) * rs * g4.x + b4.x;
    o.y = (v.y - mean) * rs * g4.y + b4.y;
    o.z = (v.z - mean) * rs * g4.z + b4.z;
    o.w = (v.w - mean) * rs * g4.w + b4.w;
    ((float4*)g_h)[n * 32 + lane] = o;
}

// ---------------- decoder ----------------
__global__ void dec_kernel(const float* __restrict__ Wd, const float* __restrict__ bd,
                           float* __restrict__ out) {
    __shared__ float Wds[LAT * NF];
    int tid = threadIdx.x;
    for (int i = tid; i < LAT * NF; i += 256) Wds[i] = Wd[i];
    __syncthreads();
    int warp = tid >> 5, lane = tid & 31;
    int n = blockIdx.x * 8 + warp;
    if (n >= NN) return;
    float4 hv = ((const float4*)g_h)[n * 32 + lane];
#pragma unroll
    for (int f = 0; f < NF; f++) {
        float p = hv.x * Wds[(lane * 4 + 0) * NF + f] +
                  hv.y * Wds[(lane * 4 + 1) * NF + f] +
                  hv.z * Wds[(lane * 4 + 2) * NF + f] +
                  hv.w * Wds[(lane * 4 + 3) * NF + f];
#pragma unroll
        for (int o = 16; o; o >>= 1) p += __shfl_xor_sync(0xFFFFFFFFu, p, o);
        if (lane == 0) out[n * NF + f] = p + bd[f];
    }
}

// ---------------- launch ----------------
extern "C" void kernel_launch(void* const* d_in, const int* in_sizes, int n_in,
                              void* d_out, int out_size) {
    const float* nodes    = (const float*)d_in[0];
    const int*   senders  = (const int*)d_in[1];
    const int*   receivers= (const int*)d_in[2];
    const float* W_embed  = (const float*)d_in[3];
    const float* b_embed  = (const float*)d_in[4];
    const float* mlp_W    = (const float*)d_in[5];
    const float* mlp_b    = (const float*)d_in[6];
    const float* ln_scale = (const float*)d_in[7];
    const float* ln_bias  = (const float*)d_in[8];
    const float* W_dec    = (const float*)d_in[9];
    const float* b_dec    = (const float*)d_in[10];
    float* out = (float*)d_out;

    const int SMEM_BYTES = (2 * LAT * LAT + 128 * AP) * (int)sizeof(float);  // 198656
    cudaFuncSetAttribute((const void*)mlp_kernel,
                         cudaFuncAttributeMaxDynamicSharedMemorySize, SMEM_BYTES);

    float *p_h, *p_x, *p_invs;
    cudaGetSymbolAddress((void**)&p_h, g_h);
    cudaGetSymbolAddress((void**)&p_x, g_x);
    cudaGetSymbolAddress((void**)&p_invs, g_invs);

    const int NB_SCAN = (NN + 1023) / 1024;   // 49
    const int mlp_grid = (NN + 127) / 128;    // 391

    // launch order: mlp is the 4th launch -> profiled by ncu
    embed_kernel<<<(NN + 7) / 8, 256>>>(nodes, W_embed, b_embed);           // 1
    deg_kernel<<<(NE + 255) / 256, 256>>>(senders, receivers);              // 2
    scan1_kernel<<<NB_SCAN, 1024>>>();                                      // 3 (also invsqrt)

    for (int s = 0; s < 3; s++) {
        const float* W1 = mlp_W + (size_t)(s * 2 + 0) * LAT * LAT;
        const float* W2 = mlp_W + (size_t)(s * 2 + 1) * LAT * LAT;
        const float* b1 = mlp_b + (size_t)(s * 2 + 0) * LAT;
        const float* b2 = mlp_b + (size_t)(s * 2 + 1) * LAT;

        mlp_kernel<<<mlp_grid, 512, SMEM_BYTES>>>(p_h, W1, W2, b1, b2, p_invs, p_x);  // 4 on s=0

        if (s == 0) {
            scan2_kernel<<<1, 64>>>(NB_SCAN);
            scan3_kernel<<<NB_SCAN, 1024>>>();
            place_kernel<<<(NE + 255) / 256, 256>>>(senders, receivers);
        }
        gather_ln_kernel<<<(NN + 7) / 8, 256>>>(ln_scale + s * LAT, ln_bias + s * LAT);
    }

    dec_kernel<<<(NN + 7) / 8, 256>>>(W_dec, b_dec, out);
}

// round 5
// speedup vs baseline: 2.5787x; 1.7322x over previous
#include <cuda_runtime.h>
#include <cuda_bf16.h>

#define NN 50000
#define NE 600000
#define LAT 128
#define NF 7
#define TILES 391          // ceil(NN/128)
#define PA 136             // bf16 elems per image row (272B: conflict-free ldmatrix)
#define IMG_BYTES (128 * PA * 2)   // 34816

// smem layout (bytes) for mlp kernel
#define SM_A_HI 0
#define SM_A_LO (SM_A_HI + IMG_BYTES)
#define SM_W1H  (SM_A_LO + IMG_BYTES)
#define SM_W1L  (SM_W1H + IMG_BYTES)
#define SM_W2H  (SM_W1L + IMG_BYTES)
#define SM_W2L  (SM_W2H + IMG_BYTES)
#define SM_BIAS (SM_W2L + IMG_BYTES)       // 208896
#define SM_TOTAL (SM_BIAS + 1024)          // 209920

// ---------------- scratch ----------------
__device__ float g_h[NN * LAT];
__device__ float g_x[NN * LAT];
__device__ float g_degs[NN];
__device__ float g_degr[NN];
__device__ float g_invs[NN];
__device__ float g_invr[NN];
__device__ int   g_off[NN + 1];
__device__ int   g_cursor[NN];
__device__ int   g_esrc[NE];
__device__ int   g_bsum[64];
__device__ unsigned char g_ahi[(size_t)TILES * IMG_BYTES];
__device__ unsigned char g_alo[(size_t)TILES * IMG_BYTES];
__device__ unsigned char g_wimg[6 * 2 * IMG_BYTES];  // [step*2+layer][hi|lo]

// ---------------- helpers ----------------
__device__ __forceinline__ unsigned smem_u32(const void* p) {
    unsigned a;
    asm("{ .reg .u64 t; cvta.to.shared.u64 t, %1; cvt.u32.u64 %0, t; }"
        : "=r"(a) : "l"(p));
    return a;
}
__device__ __forceinline__ void split_pair(float v0, float v1, unsigned& hi, unsigned& lo) {
    __nv_bfloat16 h0 = __float2bfloat16(v0);
    __nv_bfloat16 h1 = __float2bfloat16(v1);
    __nv_bfloat16 l0 = __float2bfloat16(v0 - __bfloat162float(h0));
    __nv_bfloat16 l1 = __float2bfloat16(v1 - __bfloat162float(h1));
    __nv_bfloat162 H = __halves2bfloat162(h0, h1);
    __nv_bfloat162 L = __halves2bfloat162(l0, l1);
    hi = *reinterpret_cast<unsigned*>(&H);
    lo = *reinterpret_cast<unsigned*>(&L);
}
// write node n's 4 columns (k0=lane*4) into the bf16 hi/lo tile images
__device__ __forceinline__ void store_h_image(int n, int lane, float4 v) {
    int tile = n >> 7, r = n & 127;
    unsigned h0, l0, h1, l1;
    split_pair(v.x, v.y, h0, l0);
    split_pair(v.z, v.w, h1, l1);
    size_t off = (size_t)tile * IMG_BYTES + ((size_t)r * PA + lane * 4) * 2;
    *(uint2*)(g_ahi + off) = make_uint2(h0, h1);
    *(uint2*)(g_alo + off) = make_uint2(l0, l1);
}
__device__ __forceinline__ void ldsm4(unsigned* r, unsigned addr) {
    asm volatile("ldmatrix.sync.aligned.m8n8.x4.shared.b16 {%0,%1,%2,%3}, [%4];"
                 : "=r"(r[0]), "=r"(r[1]), "=r"(r[2]), "=r"(r[3]) : "r"(addr));
}
__device__ __forceinline__ void ldsm4t(unsigned* r, unsigned addr) {
    asm volatile("ldmatrix.sync.aligned.m8n8.x4.trans.shared.b16 {%0,%1,%2,%3}, [%4];"
                 : "=r"(r[0]), "=r"(r[1]), "=r"(r[2]), "=r"(r[3]) : "r"(addr));
}
__device__ __forceinline__ void mma16816(float* d, const unsigned* a, const unsigned* b) {
    asm volatile(
        "mma.sync.aligned.m16n8k16.row.col.f32.bf16.bf16.f32 "
        "{%0,%1,%2,%3}, {%4,%5,%6,%7}, {%8,%9}, {%0,%1,%2,%3};"
        : "+f"(d[0]), "+f"(d[1]), "+f"(d[2]), "+f"(d[3])
        : "r"(a[0]), "r"(a[1]), "r"(a[2]), "r"(a[3]), "r"(b[0]), "r"(b[1]));
}

// ---------------- embed + deg-zero + weight-image build ----------------
__global__ void embed_kernel(const float* __restrict__ nodes,
                             const float* __restrict__ We,
                             const float* __restrict__ be,
                             const float* __restrict__ mlpW) {
    __shared__ float Wsh[NF * LAT];
    __shared__ float bsh[LAT];
    int tid = threadIdx.x;
    int gid = blockIdx.x * 256 + tid;
    if (gid < NN) { g_degs[gid] = 0.f; g_degr[gid] = 0.f; }
    // weight tile images: 6 layers x [k][j] pitch-136 bf16, hi/lo split
    if (gid < 6 * LAT * LAT) {
        int sl = gid >> 14;
        int rem = gid & 16383;
        int k = rem >> 7;
        int j = rem & 127;
        float w = mlpW[(size_t)sl * LAT * LAT + k * LAT + j];
        __nv_bfloat16 h = __float2bfloat16(w);
        __nv_bfloat16 l = __float2bfloat16(w - __bfloat162float(h));
        size_t off = (size_t)sl * 2 * IMG_BYTES + ((size_t)k * PA + j) * 2;
        *(__nv_bfloat16*)(g_wimg + off) = h;
        *(__nv_bfloat16*)(g_wimg + off + IMG_BYTES) = l;
    }
    for (int i = tid; i < NF * LAT; i += 256) Wsh[i] = We[i];
    if (tid < LAT) bsh[tid] = be[tid];
    __syncthreads();
    int warp = tid >> 5, lane = tid & 31;
    int n = blockIdx.x * 8 + warp;
    if (n >= NN) return;
    float t = (lane < NF) ? nodes[n * NF + lane] : 0.f;
    float f[NF];
#pragma unroll
    for (int k = 0; k < NF; k++) f[k] = __shfl_sync(0xFFFFFFFFu, t, k);
    int c0 = lane * 4;
    float4 o = make_float4(bsh[c0], bsh[c0 + 1], bsh[c0 + 2], bsh[c0 + 3]);
#pragma unroll
    for (int k = 0; k < NF; k++) {
        float4 w = *(const float4*)(Wsh + k * LAT + c0);
        o.x = fmaf(f[k], w.x, o.x);
        o.y = fmaf(f[k], w.y, o.y);
        o.z = fmaf(f[k], w.z, o.z);
        o.w = fmaf(f[k], w.w, o.w);
    }
    ((float4*)g_h)[n * 32 + lane] = o;
    store_h_image(n, lane, o);
}

__global__ void deg_kernel(const int* __restrict__ s, const int* __restrict__ r) {
    int e = blockIdx.x * blockDim.x + threadIdx.x;
    if (e < NE) {
        atomicAdd(&g_degs[s[e]], 1.f);
        atomicAdd(&g_degr[r[e]], 1.f);
    }
}

// ---------------- scans ----------------
__global__ void scan1_kernel() {
    int i = blockIdx.x * 1024 + threadIdx.x;
    int v = 0;
    if (i < NN) {
        float ds = g_degs[i], dr = g_degr[i];
        g_invs[i] = rsqrtf(fmaxf(ds, 1.f));
        g_invr[i] = rsqrtf(fmaxf(dr, 1.f));
        v = (int)dr;
    }
#pragma unroll
    for (int o = 16; o; o >>= 1) v += __shfl_xor_sync(0xFFFFFFFFu, v, o);
    __shared__ int ws[32];
    int lane = threadIdx.x & 31, warp = threadIdx.x >> 5;
    if (lane == 0) ws[warp] = v;
    __syncthreads();
    if (warp == 0) {
        int t = ws[lane];
#pragma unroll
        for (int o = 16; o; o >>= 1) t += __shfl_xor_sync(0xFFFFFFFFu, t, o);
        if (lane == 0) g_bsum[blockIdx.x] = t;
    }
}

__global__ void scan2_kernel(int nblocks) {
    int t = threadIdx.x;  // 64
    int v = (t < nblocks) ? g_bsum[t] : 0;
    int x = v;
#pragma unroll
    for (int o = 1; o < 32; o <<= 1) {
        int y = __shfl_up_sync(0xFFFFFFFFu, x, o);
        if ((t & 31) >= o) x += y;
    }
    __shared__ int w0sum;
    if (t == 31) w0sum = x;
    __syncthreads();
    if (t >= 32) x += w0sum;
    if (t < nblocks) g_bsum[t] = x - v;
}

__global__ void scan3_kernel() {
    int i = blockIdx.x * 1024 + threadIdx.x;
    int lane = threadIdx.x & 31, warp = threadIdx.x >> 5;
    int v = (i < NN) ? (int)g_degr[i] : 0;
    int x = v;
#pragma unroll
    for (int o = 1; o < 32; o <<= 1) {
        int y = __shfl_up_sync(0xFFFFFFFFu, x, o);
        if (lane >= o) x += y;
    }
    __shared__ int ws[32];
    if (lane == 31) ws[warp] = x;
    __syncthreads();
    if (warp == 0) {
        int t = ws[lane];
        int xx = t;
#pragma unroll
        for (int o = 1; o < 32; o <<= 1) {
            int y = __shfl_up_sync(0xFFFFFFFFu, xx, o);
            if (lane >= o) xx += y;
        }
        ws[lane] = xx - t;
    }
    __syncthreads();
    int ex = x - v + ws[warp] + g_bsum[blockIdx.x];
    if (i < NN) { g_off[i] = ex; g_cursor[i] = ex; }
    if (i == 0) g_off[NN] = NE;
}

__global__ void place_kernel(const int* __restrict__ snd, const int* __restrict__ rcv) {
    int e = blockIdx.x * blockDim.x + threadIdx.x;
    if (e < NE) {
        int pos = atomicAdd(&g_cursor[rcv[e]], 1);
        g_esrc[pos] = snd[e];
    }
}

// ---------------- tensor-core (mma.sync bf16x3) fused 2-layer MLP ----------------
// One warp-layer mainloop: acc += Ahi*Whi + Ahi*Wlo + Alo*Whi over K=128.
__device__ __forceinline__ void mma_layer(unsigned sAh, unsigned sAl, unsigned sWh,
                                          unsigned sWl, float acc[2][8][4],
                                          int lane, int row_w, int col_w) {
    int lr = lane & 15, lc = lane >> 4;       // A ldmatrix lane mapping
    int br = lane & 7, bseg = lane >> 3;      // B ldmatrix lane mapping
    unsigned a_base = ((row_w + lr) * PA + lc * 8) * 2;
    unsigned b_base = (((bseg & 1) * 8 + br) * PA + col_w + (bseg >> 1) * 8) * 2;

#pragma unroll 1
    for (int kt = 0; kt < 8; kt++) {
        unsigned a_off = a_base + kt * 32;            // k0*2
        unsigned b_off = b_base + kt * (16 * PA * 2); // k0*PA*2
        unsigned ah[2][4], al[2][4];
        ldsm4(ah[0], sAh + a_off);
        ldsm4(ah[1], sAh + a_off + 16 * PA * 2);
        unsigned wh[4][4], wl[4][4];
#pragma unroll
        for (int g = 0; g < 4; g++) {
            ldsm4t(wh[g], sWh + b_off + g * 32);
            ldsm4t(wl[g], sWl + b_off + g * 32);
        }
        ldsm4(al[0], sAl + a_off);
        ldsm4(al[1], sAl + a_off + 16 * PA * 2);
#pragma unroll
        for (int mt = 0; mt < 2; mt++)
#pragma unroll
            for (int nt = 0; nt < 8; nt++) {
                const unsigned* bh = &wh[nt >> 1][(nt & 1) * 2];
                const unsigned* bl = &wl[nt >> 1][(nt & 1) * 2];
                mma16816(acc[mt][nt], ah[mt], bh);
                mma16816(acc[mt][nt], ah[mt], bl);
                mma16816(acc[mt][nt], al[mt], bh);
            }
    }
}

__global__ void __launch_bounds__(256)
mlp_mma_kernel(int step, const float* __restrict__ b1g, const float* __restrict__ b2g) {
    extern __shared__ unsigned char smem[];
    unsigned sb = smem_u32(smem);
    int tid = threadIdx.x, wid = tid >> 5, lane = tid & 31;
    int row_w = (wid >> 1) * 32;   // warp M origin
    int col_w = (wid & 1) * 64;    // warp N origin
    float* b1s = (float*)(smem + SM_BIAS);
    float* b2s = (float*)(smem + SM_BIAS + 512);

    // fill smem: A hi/lo + 4 weight images + biases
    {
        const float4* srcA = (const float4*)(g_ahi + (size_t)blockIdx.x * IMG_BYTES);
        const float4* srcL = (const float4*)(g_alo + (size_t)blockIdx.x * IMG_BYTES);
        float4* dstA = (float4*)(smem + SM_A_HI);
        float4* dstL = (float4*)(smem + SM_A_LO);
        for (int i = tid; i < IMG_BYTES / 16; i += 256) {
            dstA[i] = srcA[i];
            dstL[i] = srcL[i];
        }
        const float4* srcW = (const float4*)(g_wimg + (size_t)step * 4 * IMG_BYTES);
        float4* dstW = (float4*)(smem + SM_W1H);
        for (int i = tid; i < 4 * IMG_BYTES / 16; i += 256) dstW[i] = srcW[i];
        if (tid < 128) b1s[tid] = b1g[tid];
        else b2s[tid - 128] = b2g[tid - 128];
    }
    __syncthreads();

    float acc[2][8][4];
#pragma unroll
    for (int mt = 0; mt < 2; mt++)
#pragma unroll
        for (int nt = 0; nt < 8; nt++)
#pragma unroll
            for (int q = 0; q < 4; q++) acc[mt][nt][q] = 0.f;

    // ---- layer 1 ----
    mma_layer(sb + SM_A_HI, sb + SM_A_LO, sb + SM_W1H, sb + SM_W1L, acc,
              lane, row_w, col_w);
    __syncthreads();  // all A reads done before overwrite

    int qr = lane >> 2;            // 0..7
    int qc = (lane & 3) * 2;       // 0,2,4,6
#pragma unroll
    for (int mt = 0; mt < 2; mt++)
#pragma unroll
        for (int nt = 0; nt < 8; nt++) {
            int r0 = row_w + mt * 16 + qr;
            int c = col_w + nt * 8 + qc;
            float v00 = fmaxf(acc[mt][nt][0] + b1s[c], 0.f);
            float v01 = fmaxf(acc[mt][nt][1] + b1s[c + 1], 0.f);
            float v10 = fmaxf(acc[mt][nt][2] + b1s[c], 0.f);
            float v11 = fmaxf(acc[mt][nt][3] + b1s[c + 1], 0.f);
            unsigned h, l;
            split_pair(v00, v01, h, l);
            *(unsigned*)(smem + SM_A_HI + (r0 * PA + c) * 2) = h;
            *(unsigned*)(smem + SM_A_LO + (r0 * PA + c) * 2) = l;
            split_pair(v10, v11, h, l);
            *(unsigned*)(smem + SM_A_HI + ((r0 + 8) * PA + c) * 2) = h;
            *(unsigned*)(smem + SM_A_LO + ((r0 + 8) * PA + c) * 2) = l;
#pragma unroll
            for (int q = 0; q < 4; q++) acc[mt][nt][q] = 0.f;
        }
    __syncthreads();

    // ---- layer 2 ----
    mma_layer(sb + SM_A_HI, sb + SM_A_LO, sb + SM_W2H, sb + SM_W2L, acc,
              lane, row_w, col_w);

    // epilogue 2: relu + bias, * invs, store fp32 to g_x
#pragma unroll
    for (int mt = 0; mt < 2; mt++) {
#pragma unroll
        for (int half = 0; half < 2; half++) {
            int r = row_w + mt * 16 + half * 8 + qr;
            int node = blockIdx.x * 128 + r;
            if (node < NN) {
                float sc = g_invs[node];
#pragma unroll
                for (int nt = 0; nt < 8; nt++) {
                    int c = col_w + nt * 8 + qc;
                    float2 o;
                    o.x = fmaxf(acc[mt][nt][2 * half] + b2s[c], 0.f) * sc;
                    o.y = fmaxf(acc[mt][nt][2 * half + 1] + b2s[c + 1], 0.f) * sc;
                    *(float2*)(g_x + (size_t)node * LAT + c) = o;
                }
            }
        }
    }
}

// ---------------- fused CSR-gather + skip + inv_sqrt_r + layernorm ----------------
__global__ void gather_ln_kernel(const float* __restrict__ lns,
                                 const float* __restrict__ lnb, int write_img) {
    int gw = (blockIdx.x * blockDim.x + threadIdx.x) >> 5;
    if (gw >= NN) return;
    int lane = threadIdx.x & 31;
    int n = gw;
    int beg = g_off[n], end = g_off[n + 1];

    const float4* X = (const float4*)g_x;
    float4 acc = make_float4(0.f, 0.f, 0.f, 0.f);
    int i = beg;
    for (; i + 3 < end; i += 4) {
        int s0 = g_esrc[i], s1 = g_esrc[i + 1], s2 = g_esrc[i + 2], s3 = g_esrc[i + 3];
        float4 v0 = __ldg(&X[s0 * 32 + lane]);
        float4 v1 = __ldg(&X[s1 * 32 + lane]);
        float4 v2 = __ldg(&X[s2 * 32 + lane]);
        float4 v3 = __ldg(&X[s3 * 32 + lane]);
        acc.x += v0.x + v1.x + v2.x + v3.x;
        acc.y += v0.y + v1.y + v2.y + v3.y;
        acc.z += v0.z + v1.z + v2.z + v3.z;
        acc.w += v0.w + v1.w + v2.w + v3.w;
    }
    for (; i < end; i++) {
        int s = g_esrc[i];
        float4 v = __ldg(&X[s * 32 + lane]);
        acc.x += v.x; acc.y += v.y; acc.z += v.z; acc.w += v.w;
    }

    float ir = g_invr[n];
    float4 h4 = ((const float4*)g_h)[n * 32 + lane];
    float4 v;
    v.x = h4.x + acc.x * ir;
    v.y = h4.y + acc.y * ir;
    v.z = h4.z + acc.z * ir;
    v.w = h4.w + acc.w * ir;

    float s1 = v.x + v.y + v.z + v.w;
    float s2 = v.x * v.x + v.y * v.y + v.z * v.z + v.w * v.w;
#pragma unroll
    for (int o = 16; o; o >>= 1) {
        s1 += __shfl_xor_sync(0xFFFFFFFFu, s1, o);
        s2 += __shfl_xor_sync(0xFFFFFFFFu, s2, o);
    }
    float mean = s1 * (1.f / 128.f);
    float var = s2 * (1.f / 128.f) - mean * mean;
    float rs = rsqrtf(var + 1e-6f);

    float4 g4 = __ldg(&((const float4*)lns)[lane]);
    float4 b4 = __ldg(&((const float4*)lnb)[lane]);
    float4 o;
    o.x = (v.x - mean) * rs * g4.x + b4.x;
    o.y = (v.y - mean) * rs * g4.y + b4.y;
    o.z = (v.z - mean) * rs * g4.z + b4.z;
    o.w = (v.w - mean) * rs * g4.w + b4.w;
    ((float4*)g_h)[n * 32 + lane] = o;
    if (write_img) store_h_image(n, lane, o);
}

// ---------------- decoder ----------------
__global__ void dec_kernel(const float* __restrict__ Wd, const float* __restrict__ bd,
                           float* __restrict__ out) {
    __shared__ float Wds[LAT * NF];
    int tid = threadIdx.x;
    for (int i = tid; i < LAT * NF; i += 256) Wds[i] = Wd[i];
    __syncthreads();
    int warp = tid >> 5, lane = tid & 31;
    int n = blockIdx.x * 8 + warp;
    if (n >= NN) return;
    float4 hv = ((const float4*)g_h)[n * 32 + lane];
#pragma unroll
    for (int f = 0; f < NF; f++) {
        float p = hv.x * Wds[(lane * 4 + 0) * NF + f] +
                  hv.y * Wds[(lane * 4 + 1) * NF + f] +
                  hv.z * Wds[(lane * 4 + 2) * NF + f] +
                  hv.w * Wds[(lane * 4 + 3) * NF + f];
#pragma unroll
        for (int o = 16; o; o >>= 1) p += __shfl_xor_sync(0xFFFFFFFFu, p, o);
        if (lane == 0) out[n * NF + f] = p + bd[f];
    }
}

// ---------------- launch ----------------
extern "C" void kernel_launch(void* const* d_in, const int* in_sizes, int n_in,
                              void* d_out, int out_size) {
    const float* nodes    = (const float*)d_in[0];
    const int*   senders  = (const int*)d_in[1];
    const int*   receivers= (const int*)d_in[2];
    const float* W_embed  = (const float*)d_in[3];
    const float* b_embed  = (const float*)d_in[4];
    const float* mlp_W    = (const float*)d_in[5];
    const float* mlp_b    = (const float*)d_in[6];
    const float* ln_scale = (const float*)d_in[7];
    const float* ln_bias  = (const float*)d_in[8];
    const float* W_dec    = (const float*)d_in[9];
    const float* b_dec    = (const float*)d_in[10];
    float* out = (float*)d_out;

    cudaFuncSetAttribute((const void*)mlp_mma_kernel,
                         cudaFuncAttributeMaxDynamicSharedMemorySize, SM_TOTAL);

    const int NB_SCAN = (NN + 1023) / 1024;  // 49

    // order: mlp step0 is the 4th launch (ncu capture slot)
    embed_kernel<<<(NN + 7) / 8, 256>>>(nodes, W_embed, b_embed, mlp_W);  // 1
    deg_kernel<<<(NE + 255) / 256, 256>>>(senders, receivers);            // 2
    scan1_kernel<<<NB_SCAN, 1024>>>();                                    // 3

    for (int s = 0; s < 3; s++) {
        const float* b1 = mlp_b + (size_t)(s * 2 + 0) * LAT;
        const float* b2 = mlp_b + (size_t)(s * 2 + 1) * LAT;
        mlp_mma_kernel<<<TILES, 256, SM_TOTAL>>>(s, b1, b2);              // 4 on s=0
        if (s == 0) {
            scan2_kernel<<<1, 64>>>(NB_SCAN);
            scan3_kernel<<<NB_SCAN, 1024>>>();
            place_kernel<<<(NE + 255) / 256, 256>>>(senders, receivers);
        }
        gather_ln_kernel<<<(NN + 7) / 8, 256>>>(ln_scale + s * LAT, ln_bias + s * LAT,
                                                s < 2 ? 1 : 0);
    }

    dec_kernel<<<(NN + 7) / 8, 256>>>(W_dec, b_dec, out);
}

// round 6
// speedup vs baseline: 3.1251x; 1.2119x over previous
#include <cuda_runtime.h>
#include <cuda_bf16.h>

#define NN 50000
#define NE 600000
#define LAT 128
#define NF 7
#define TILES 391          // ceil(NN/128)
#define PA 136             // bf16 elems per image row (272B: conflict-free ldmatrix)
#define IMG_BYTES (128 * PA * 2)   // 34816

// smem layout (bytes) for mlp kernel
#define SM_A_HI 0
#define SM_A_LO (SM_A_HI + IMG_BYTES)
#define SM_W1H  (SM_A_LO + IMG_BYTES)
#define SM_W1L  (SM_W1H + IMG_BYTES)
#define SM_W2H  (SM_W1L + IMG_BYTES)
#define SM_W2L  (SM_W2H + IMG_BYTES)
#define SM_BIAS (SM_W2L + IMG_BYTES)       // 208896
#define SM_TOTAL (SM_BIAS + 1024)          // 209920

// ---------------- scratch ----------------
__device__ float g_h[NN * LAT];
__device__ float g_x[NN * LAT];
__device__ float g_degs[NN];
__device__ float g_degr[NN];
__device__ float g_invs[NN];
__device__ float g_invr[NN];
__device__ int   g_off[NN + 1];
__device__ int   g_cursor[NN];
__device__ int   g_esrc[NE];
__device__ int   g_bsum[64];
__device__ unsigned char g_ahi[(size_t)TILES * IMG_BYTES];
__device__ unsigned char g_alo[(size_t)TILES * IMG_BYTES];
__device__ unsigned char g_wimg[6 * 2 * IMG_BYTES];  // [step*2+layer][hi|lo]

// ---------------- helpers ----------------
__device__ __forceinline__ unsigned smem_u32(const void* p) {
    unsigned a;
    asm("{ .reg .u64 t; cvta.to.shared.u64 t, %1; cvt.u32.u64 %0, t; }"
        : "=r"(a) : "l"(p));
    return a;
}
__device__ __forceinline__ void cpasync16(unsigned s, const void* g) {
    asm volatile("cp.async.cg.shared.global [%0], [%1], 16;" :: "r"(s), "l"(g));
}
__device__ __forceinline__ void split_pair(float v0, float v1, unsigned& hi, unsigned& lo) {
    __nv_bfloat16 h0 = __float2bfloat16(v0);
    __nv_bfloat16 h1 = __float2bfloat16(v1);
    __nv_bfloat16 l0 = __float2bfloat16(v0 - __bfloat162float(h0));
    __nv_bfloat16 l1 = __float2bfloat16(v1 - __bfloat162float(h1));
    __nv_bfloat162 H = __halves2bfloat162(h0, h1);
    __nv_bfloat162 L = __halves2bfloat162(l0, l1);
    hi = *reinterpret_cast<unsigned*>(&H);
    lo = *reinterpret_cast<unsigned*>(&L);
}
__device__ __forceinline__ void store_h_image(int n, int lane, float4 v) {
    int tile = n >> 7, r = n & 127;
    unsigned h0, l0, h1, l1;
    split_pair(v.x, v.y, h0, l0);
    split_pair(v.z, v.w, h1, l1);
    size_t off = (size_t)tile * IMG_BYTES + ((size_t)r * PA + lane * 4) * 2;
    *(uint2*)(g_ahi + off) = make_uint2(h0, h1);
    *(uint2*)(g_alo + off) = make_uint2(l0, l1);
}
__device__ __forceinline__ void ldsm4(unsigned* r, unsigned addr) {
    asm volatile("ldmatrix.sync.aligned.m8n8.x4.shared.b16 {%0,%1,%2,%3}, [%4];"
                 : "=r"(r[0]), "=r"(r[1]), "=r"(r[2]), "=r"(r[3]) : "r"(addr));
}
__device__ __forceinline__ void ldsm4t(unsigned* r, unsigned addr) {
    asm volatile("ldmatrix.sync.aligned.m8n8.x4.trans.shared.b16 {%0,%1,%2,%3}, [%4];"
                 : "=r"(r[0]), "=r"(r[1]), "=r"(r[2]), "=r"(r[3]) : "r"(addr));
}
__device__ __forceinline__ void mma16816(float* d, const unsigned* a, const unsigned* b) {
    asm volatile(
        "mma.sync.aligned.m16n8k16.row.col.f32.bf16.bf16.f32 "
        "{%0,%1,%2,%3}, {%4,%5,%6,%7}, {%8,%9}, {%0,%1,%2,%3};"
        : "+f"(d[0]), "+f"(d[1]), "+f"(d[2]), "+f"(d[3])
        : "r"(a[0]), "r"(a[1]), "r"(a[2]), "r"(a[3]), "r"(b[0]), "r"(b[1]));
}

// ---------------- embed + deg-zero + weight-image build ----------------
__global__ void embed_kernel(const float* __restrict__ nodes,
                             const float* __restrict__ We,
                             const float* __restrict__ be,
                             const float* __restrict__ mlpW) {
    __shared__ float Wsh[NF * LAT];
    __shared__ float bsh[LAT];
    int tid = threadIdx.x;
    int gid = blockIdx.x * 256 + tid;
    if (gid < NN) { g_degs[gid] = 0.f; g_degr[gid] = 0.f; }
    if (gid < 6 * LAT * LAT) {
        int sl = gid >> 14;
        int rem = gid & 16383;
        int k = rem >> 7;
        int j = rem & 127;
        float w = mlpW[(size_t)sl * LAT * LAT + k * LAT + j];
        __nv_bfloat16 h = __float2bfloat16(w);
        __nv_bfloat16 l = __float2bfloat16(w - __bfloat162float(h));
        size_t off = (size_t)sl * 2 * IMG_BYTES + ((size_t)k * PA + j) * 2;
        *(__nv_bfloat16*)(g_wimg + off) = h;
        *(__nv_bfloat16*)(g_wimg + off + IMG_BYTES) = l;
    }
    for (int i = tid; i < NF * LAT; i += 256) Wsh[i] = We[i];
    if (tid < LAT) bsh[tid] = be[tid];
    __syncthreads();
    int warp = tid >> 5, lane = tid & 31;
    int n = blockIdx.x * 8 + warp;
    if (n >= NN) return;
    float t = (lane < NF) ? nodes[n * NF + lane] : 0.f;
    float f[NF];
#pragma unroll
    for (int k = 0; k < NF; k++) f[k] = __shfl_sync(0xFFFFFFFFu, t, k);
    int c0 = lane * 4;
    float4 o = make_float4(bsh[c0], bsh[c0 + 1], bsh[c0 + 2], bsh[c0 + 3]);
#pragma unroll
    for (int k = 0; k < NF; k++) {
        float4 w = *(const float4*)(Wsh + k * LAT + c0);
        o.x = fmaf(f[k], w.x, o.x);
        o.y = fmaf(f[k], w.y, o.y);
        o.z = fmaf(f[k], w.z, o.z);
        o.w = fmaf(f[k], w.w, o.w);
    }
    ((float4*)g_h)[n * 32 + lane] = o;
    store_h_image(n, lane, o);
}

__global__ void deg_kernel(const int* __restrict__ s, const int* __restrict__ r) {
    int e = blockIdx.x * blockDim.x + threadIdx.x;
    if (e < NE) {
        atomicAdd(&g_degs[s[e]], 1.f);
        atomicAdd(&g_degr[r[e]], 1.f);
    }
}

// ---------------- scans ----------------
__global__ void scan1_kernel() {
    int i = blockIdx.x * 1024 + threadIdx.x;
    int v = 0;
    if (i < NN) {
        float ds = g_degs[i], dr = g_degr[i];
        g_invs[i] = rsqrtf(fmaxf(ds, 1.f));
        g_invr[i] = rsqrtf(fmaxf(dr, 1.f));
        v = (int)dr;
    }
#pragma unroll
    for (int o = 16; o; o >>= 1) v += __shfl_xor_sync(0xFFFFFFFFu, v, o);
    __shared__ int ws[32];
    int lane = threadIdx.x & 31, warp = threadIdx.x >> 5;
    if (lane == 0) ws[warp] = v;
    __syncthreads();
    if (warp == 0) {
        int t = ws[lane];
#pragma unroll
        for (int o = 16; o; o >>= 1) t += __shfl_xor_sync(0xFFFFFFFFu, t, o);
        if (lane == 0) g_bsum[blockIdx.x] = t;
    }
}

__global__ void scan2_kernel(int nblocks) {
    int t = threadIdx.x;  // 64
    int v = (t < nblocks) ? g_bsum[t] : 0;
    int x = v;
#pragma unroll
    for (int o = 1; o < 32; o <<= 1) {
        int y = __shfl_up_sync(0xFFFFFFFFu, x, o);
        if ((t & 31) >= o) x += y;
    }
    __shared__ int w0sum;
    if (t == 31) w0sum = x;
    __syncthreads();
    if (t >= 32) x += w0sum;
    if (t < nblocks) g_bsum[t] = x - v;
}

__global__ void scan3_kernel() {
    int i = blockIdx.x * 1024 + threadIdx.x;
    int lane = threadIdx.x & 31, warp = threadIdx.x >> 5;
    int v = (i < NN) ? (int)g_degr[i] : 0;
    int x = v;
#pragma unroll
    for (int o = 1; o < 32; o <<= 1) {
        int y = __shfl_up_sync(0xFFFFFFFFu, x, o);
        if (lane >= o) x += y;
    }
    __shared__ int ws[32];
    if (lane == 31) ws[warp] = x;
    __syncthreads();
    if (warp == 0) {
        int t = ws[lane];
        int xx = t;
#pragma unroll
        for (int o = 1; o < 32; o <<= 1) {
            int y = __shfl_up_sync(0xFFFFFFFFu, xx, o);
            if (lane >= o) xx += y;
        }
        ws[lane] = xx - t;
    }
    __syncthreads();
    int ex = x - v + ws[warp] + g_bsum[blockIdx.x];
    if (i < NN) { g_off[i] = ex; g_cursor[i] = ex; }
    if (i == 0) g_off[NN] = NE;
}

__global__ void place_kernel(const int* __restrict__ snd, const int* __restrict__ rcv) {
    int e = blockIdx.x * blockDim.x + threadIdx.x;
    if (e < NE) {
        int pos = atomicAdd(&g_cursor[rcv[e]], 1);
        g_esrc[pos] = snd[e];
    }
}

// ---------------- mma.sync bf16x3 fused 2-layer MLP (16 warps) ----------------
// warp tile 32M x 32N; acc[2 mt][4 nt][4]
__device__ __forceinline__ void mma_layer(unsigned sAh, unsigned sAl, unsigned sWh,
                                          unsigned sWl, float acc[2][4][4],
                                          int lane, int row_w, int col_w) {
    int lr = lane & 15, lc = lane >> 4;       // A ldmatrix lane mapping
    int br = lane & 7, bseg = lane >> 3;      // B ldmatrix lane mapping
    unsigned a_base = ((row_w + lr) * PA + lc * 8) * 2;
    unsigned b_base = (((bseg & 1) * 8 + br) * PA + col_w + (bseg >> 1) * 8) * 2;

#pragma unroll 1
    for (int kt = 0; kt < 8; kt++) {
        unsigned a_off = a_base + kt * 32;            // k0*2 bytes
        unsigned b_off = b_base + kt * (16 * PA * 2); // k0 rows
        unsigned ah[2][4], al[2][4];
        ldsm4(ah[0], sAh + a_off);
        ldsm4(ah[1], sAh + a_off + 16 * PA * 2);
        unsigned wh[2][4], wl[2][4];
#pragma unroll
        for (int g = 0; g < 2; g++) {
            ldsm4t(wh[g], sWh + b_off + g * 32);
            ldsm4t(wl[g], sWl + b_off + g * 32);
        }
        ldsm4(al[0], sAl + a_off);
        ldsm4(al[1], sAl + a_off + 16 * PA * 2);
#pragma unroll
        for (int mt = 0; mt < 2; mt++)
#pragma unroll
            for (int nt = 0; nt < 4; nt++) {
                const unsigned* bh = &wh[nt >> 1][(nt & 1) * 2];
                const unsigned* bl = &wl[nt >> 1][(nt & 1) * 2];
                mma16816(acc[mt][nt], ah[mt], bh);
                mma16816(acc[mt][nt], ah[mt], bl);
                mma16816(acc[mt][nt], al[mt], bh);
            }
    }
}

__global__ void __launch_bounds__(512)
mlp_mma_kernel(int step, const float* __restrict__ b1g, const float* __restrict__ b2g) {
    extern __shared__ unsigned char smem[];
    unsigned sb = smem_u32(smem);
    int tid = threadIdx.x, wid = tid >> 5, lane = tid & 31;
    int row_w = (wid >> 2) * 32;   // warp M origin (0,32,64,96)
    int col_w = (wid & 3) * 32;    // warp N origin (0,32,64,96)
    float* b1s = (float*)(smem + SM_BIAS);
    float* b2s = (float*)(smem + SM_BIAS + 512);

    // async fill, group 1: A hi/lo + W1 hi/lo ; group 2: W2 hi/lo
    {
        const unsigned char* srcA = g_ahi + (size_t)blockIdx.x * IMG_BYTES;
        const unsigned char* srcL = g_alo + (size_t)blockIdx.x * IMG_BYTES;
        const unsigned char* srcW = g_wimg + (size_t)step * 4 * IMG_BYTES;
        for (int i = tid; i < IMG_BYTES / 16; i += 512) {
            cpasync16(sb + SM_A_HI + i * 16, srcA + i * 16);
            cpasync16(sb + SM_A_LO + i * 16, srcL + i * 16);
        }
        for (int i = tid; i < 2 * IMG_BYTES / 16; i += 512)
            cpasync16(sb + SM_W1H + i * 16, srcW + i * 16);
        asm volatile("cp.async.commit_group;" ::: "memory");
        for (int i = tid; i < 2 * IMG_BYTES / 16; i += 512)
            cpasync16(sb + SM_W2H + i * 16, srcW + 2 * IMG_BYTES + i * 16);
        asm volatile("cp.async.commit_group;" ::: "memory");
        if (tid < 128) b1s[tid] = b1g[tid];
        else if (tid < 256) b2s[tid - 128] = b2g[tid - 128];
    }
    asm volatile("cp.async.wait_group 1;" ::: "memory");  // A + W1 ready
    __syncthreads();

    float acc[2][4][4];
#pragma unroll
    for (int mt = 0; mt < 2; mt++)
#pragma unroll
        for (int nt = 0; nt < 4; nt++)
#pragma unroll
            for (int q = 0; q < 4; q++) acc[mt][nt][q] = 0.f;

    // ---- layer 1 ----
    mma_layer(sb + SM_A_HI, sb + SM_A_LO, sb + SM_W1H, sb + SM_W1L, acc,
              lane, row_w, col_w);
    __syncthreads();  // all A reads done before overwrite

    int qr = lane >> 2;            // 0..7
    int qc = (lane & 3) * 2;       // 0,2,4,6
#pragma unroll
    for (int mt = 0; mt < 2; mt++)
#pragma unroll
        for (int nt = 0; nt < 4; nt++) {
            int r0 = row_w + mt * 16 + qr;
            int c = col_w + nt * 8 + qc;
            float v00 = fmaxf(acc[mt][nt][0] + b1s[c], 0.f);
            float v01 = fmaxf(acc[mt][nt][1] + b1s[c + 1], 0.f);
            float v10 = fmaxf(acc[mt][nt][2] + b1s[c], 0.f);
            float v11 = fmaxf(acc[mt][nt][3] + b1s[c + 1], 0.f);
            unsigned h, l;
            split_pair(v00, v01, h, l);
            *(unsigned*)(smem + SM_A_HI + (r0 * PA + c) * 2) = h;
            *(unsigned*)(smem + SM_A_LO + (r0 * PA + c) * 2) = l;
            split_pair(v10, v11, h, l);
            *(unsigned*)(smem + SM_A_HI + ((r0 + 8) * PA + c) * 2) = h;
            *(unsigned*)(smem + SM_A_LO + ((r0 + 8) * PA + c) * 2) = l;
#pragma unroll
            for (int q = 0; q < 4; q++) acc[mt][nt][q] = 0.f;
        }
    asm volatile("cp.async.wait_group 0;" ::: "memory");  // W2 ready
    __syncthreads();

    // ---- layer 2 ----
    mma_layer(sb + SM_A_HI, sb + SM_A_LO, sb + SM_W2H, sb + SM_W2L, acc,
              lane, row_w, col_w);

    // epilogue 2: relu + bias, * invs, store fp32 to g_x
#pragma unroll
    for (int mt = 0; mt < 2; mt++) {
#pragma unroll
        for (int half = 0; half < 2; half++) {
            int r = row_w + mt * 16 + half * 8 + qr;
            int node = blockIdx.x * 128 + r;
            if (node < NN) {
                float sc = g_invs[node];
#pragma unroll
                for (int nt = 0; nt < 4; nt++) {
                    int c = col_w + nt * 8 + qc;
                    float2 o;
                    o.x = fmaxf(acc[mt][nt][2 * half] + b2s[c], 0.f) * sc;
                    o.y = fmaxf(acc[mt][nt][2 * half + 1] + b2s[c + 1], 0.f) * sc;
                    *(float2*)(g_x + (size_t)node * LAT + c) = o;
                }
            }
        }
    }
}

// ---------------- fused CSR-gather + skip + inv_sqrt_r + layernorm ----------------
__global__ void gather_ln_kernel(const float* __restrict__ lns,
                                 const float* __restrict__ lnb, int write_img) {
    int gw = (blockIdx.x * blockDim.x + threadIdx.x) >> 5;
    if (gw >= NN) return;
    int lane = threadIdx.x & 31;
    int n = gw;
    int beg = g_off[n], end = g_off[n + 1];

    const float4* X = (const float4*)g_x;
    float4 acc = make_float4(0.f, 0.f, 0.f, 0.f);
    int i = beg;
    for (; i + 3 < end; i += 4) {
        int s0 = g_esrc[i], s1 = g_esrc[i + 1], s2 = g_esrc[i + 2], s3 = g_esrc[i + 3];
        float4 v0 = __ldg(&X[s0 * 32 + lane]);
        float4 v1 = __ldg(&X[s1 * 32 + lane]);
        float4 v2 = __ldg(&X[s2 * 32 + lane]);
        float4 v3 = __ldg(&X[s3 * 32 + lane]);
        acc.x += v0.x + v1.x + v2.x + v3.x;
        acc.y += v0.y + v1.y + v2.y + v3.y;
        acc.z += v0.z + v1.z + v2.z + v3.z;
        acc.w += v0.w + v1.w + v2.w + v3.w;
    }
    for (; i < end; i++) {
        int s = g_esrc[i];
        float4 v = __ldg(&X[s * 32 + lane]);
        acc.x += v.x; acc.y += v.y; acc.z += v.z; acc.w += v.w;
    }

    float ir = g_invr[n];
    float4 h4 = ((const float4*)g_h)[n * 32 + lane];
    float4 v;
    v.x = h4.x + acc.x * ir;
    v.y = h4.y + acc.y * ir;
    v.z = h4.z + acc.z * ir;
    v.w = h4.w + acc.w * ir;

    float s1 = v.x + v.y + v.z + v.w;
    float s2 = v.x * v.x + v.y * v.y + v.z * v.z + v.w * v.w;
#pragma unroll
    for (int o = 16; o; o >>= 1) {
        s1 += __shfl_xor_sync(0xFFFFFFFFu, s1, o);
        s2 += __shfl_xor_sync(0xFFFFFFFFu, s2, o);
    }
    float mean = s1 * (1.f / 128.f);
    float var = s2 * (1.f / 128.f) - mean * mean;
    float rs = rsqrtf(var + 1e-6f);

    float4 g4 = __ldg(&((const float4*)lns)[lane]);
    float4 b4 = __ldg(&((const float4*)lnb)[lane]);
    float4 o;
    o.x = (v.x - mean) * rs * g4.x + b4.x;
    o.y = (v.y - mean) * rs * g4.y + b4.y;
    o.z = (v.z - mean) * rs * g4.z + b4.z;
    o.w = (v.w - mean) * rs * g4.w + b4.w;
    ((float4*)g_h)[n * 32 + lane] = o;
    if (write_img) store_h_image(n, lane, o);
}

// ---------------- decoder ----------------
__global__ void dec_kernel(const float* __restrict__ Wd, const float* __restrict__ bd,
                           float* __restrict__ out) {
    __shared__ float Wds[LAT * NF];
    int tid = threadIdx.x;
    for (int i = tid; i < LAT * NF; i += 256) Wds[i] = Wd[i];
    __syncthreads();
    int warp = tid >> 5, lane = tid & 31;
    int n = blockIdx.x * 8 + warp;
    if (n >= NN) return;
    float4 hv = ((const float4*)g_h)[n * 32 + lane];
#pragma unroll
    for (int f = 0; f < NF; f++) {
        float p = hv.x * Wds[(lane * 4 + 0) * NF + f] +
                  hv.y * Wds[(lane * 4 + 1) * NF + f] +
                  hv.z * Wds[(lane * 4 + 2) * NF + f] +
                  hv.w * Wds[(lane * 4 + 3) * NF + f];
#pragma unroll
        for (int o = 16; o; o >>= 1) p += __shfl_xor_sync(0xFFFFFFFFu, p, o);
        if (lane == 0) out[n * NF + f] = p + bd[f];
    }
}

// ---------------- launch ----------------
extern "C" void kernel_launch(void* const* d_in, const int* in_sizes, int n_in,
                              void* d_out, int out_size) {
    const float* nodes    = (const float*)d_in[0];
    const int*   senders  = (const int*)d_in[1];
    const int*   receivers= (const int*)d_in[2];
    const float* W_embed  = (const float*)d_in[3];
    const float* b_embed  = (const float*)d_in[4];
    const float* mlp_W    = (const float*)d_in[5];
    const float* mlp_b    = (const float*)d_in[6];
    const float* ln_scale = (const float*)d_in[7];
    const float* ln_bias  = (const float*)d_in[8];
    const float* W_dec    = (const float*)d_in[9];
    const float* b_dec    = (const float*)d_in[10];
    float* out = (float*)d_out;

    cudaFuncSetAttribute((const void*)mlp_mma_kernel,
                         cudaFuncAttributeMaxDynamicSharedMemorySize, SM_TOTAL);

    const int NB_SCAN = (NN + 1023) / 1024;  // 49

    // order: mlp step0 is the 4th launch (ncu capture slot)
    embed_kernel<<<(NN + 7) / 8, 256>>>(nodes, W_embed, b_embed, mlp_W);  // 1
    deg_kernel<<<(NE + 255) / 256, 256>>>(senders, receivers);            // 2
    scan1_kernel<<<NB_SCAN, 1024>>>();                                    // 3

    for (int s = 0; s < 3; s++) {
        const float* b1 = mlp_b + (size_t)(s * 2 + 0) * LAT;
        const float* b2 = mlp_b + (size_t)(s * 2 + 1) * LAT;
        mlp_mma_kernel<<<TILES, 512, SM_TOTAL>>>(s, b1, b2);              // 4 on s=0
        if (s == 0) {
            scan2_kernel<<<1, 64>>>(NB_SCAN);
            scan3_kernel<<<NB_SCAN, 1024>>>();
            place_kernel<<<(NE + 255) / 256, 256>>>(senders, receivers);
        }
        gather_ln_kernel<<<(NN + 7) / 8, 256>>>(ln_scale + s * LAT, ln_bias + s * LAT,
                                                s < 2 ? 1 : 0);
    }

    dec_kernel<<<(NN + 7) / 8, 256>>>(W_dec, b_dec, out);
}

// round 7
// speedup vs baseline: 3.2283x; 1.0330x over previous
#include <cuda_runtime.h>
#include <cuda_bf16.h>

#define NN 50000
#define NE 600000
#define LAT 128
#define NF 7
#define TILES 391          // ceil(NN/128)
#define NPERS 131          // persistent mlp grid (131*3 >= 391, single wave)
#define PA 136             // bf16 elems per image row (272B: conflict-free ldmatrix)
#define IMG_BYTES (128 * PA * 2)   // 34816

// smem layout (bytes) for mlp kernel
#define SM_A_HI 0
#define SM_A_LO (SM_A_HI + IMG_BYTES)
#define SM_W1H  (SM_A_LO + IMG_BYTES)
#define SM_W1L  (SM_W1H + IMG_BYTES)
#define SM_W2H  (SM_W1L + IMG_BYTES)
#define SM_W2L  (SM_W2H + IMG_BYTES)
#define SM_BIAS (SM_W2L + IMG_BYTES)       // 208896
#define SM_TOTAL (SM_BIAS + 1024)          // 209920

// ---------------- scratch ----------------
__device__ float g_h[NN * LAT];
__device__ float g_x[NN * LAT];
__device__ float g_degs[NN];
__device__ float g_degr[NN];
__device__ float g_invs[NN];
__device__ float g_invr[NN];
__device__ int   g_off[NN + 1];
__device__ int   g_cursor[NN];
__device__ int   g_esrc[NE];
__device__ int   g_bsum[64];
__device__ unsigned char g_ahi[(size_t)TILES * IMG_BYTES];
__device__ unsigned char g_alo[(size_t)TILES * IMG_BYTES];
__device__ unsigned char g_wimg[6 * 2 * IMG_BYTES];  // [step*2+layer][hi|lo]

// ---------------- helpers ----------------
__device__ __forceinline__ unsigned smem_u32(const void* p) {
    unsigned a;
    asm("{ .reg .u64 t; cvta.to.shared.u64 t, %1; cvt.u32.u64 %0, t; }"
        : "=r"(a) : "l"(p));
    return a;
}
__device__ __forceinline__ void cpasync16(unsigned s, const void* g) {
    asm volatile("cp.async.cg.shared.global [%0], [%1], 16;" :: "r"(s), "l"(g));
}
__device__ __forceinline__ void split_pair(float v0, float v1, unsigned& hi, unsigned& lo) {
    __nv_bfloat16 h0 = __float2bfloat16(v0);
    __nv_bfloat16 h1 = __float2bfloat16(v1);
    __nv_bfloat16 l0 = __float2bfloat16(v0 - __bfloat162float(h0));
    __nv_bfloat16 l1 = __float2bfloat16(v1 - __bfloat162float(h1));
    __nv_bfloat162 H = __halves2bfloat162(h0, h1);
    __nv_bfloat162 L = __halves2bfloat162(l0, l1);
    hi = *reinterpret_cast<unsigned*>(&H);
    lo = *reinterpret_cast<unsigned*>(&L);
}
__device__ __forceinline__ void store_h_image(int n, int lane, float4 v) {
    int tile = n >> 7, r = n & 127;
    unsigned h0, l0, h1, l1;
    split_pair(v.x, v.y, h0, l0);
    split_pair(v.z, v.w, h1, l1);
    size_t off = (size_t)tile * IMG_BYTES + ((size_t)r * PA + lane * 4) * 2;
    *(uint2*)(g_ahi + off) = make_uint2(h0, h1);
    *(uint2*)(g_alo + off) = make_uint2(l0, l1);
}
__device__ __forceinline__ void ldsm4(unsigned* r, unsigned addr) {
    asm volatile("ldmatrix.sync.aligned.m8n8.x4.shared.b16 {%0,%1,%2,%3}, [%4];"
                 : "=r"(r[0]), "=r"(r[1]), "=r"(r[2]), "=r"(r[3]) : "r"(addr));
}
__device__ __forceinline__ void ldsm4t(unsigned* r, unsigned addr) {
    asm volatile("ldmatrix.sync.aligned.m8n8.x4.trans.shared.b16 {%0,%1,%2,%3}, [%4];"
                 : "=r"(r[0]), "=r"(r[1]), "=r"(r[2]), "=r"(r[3]) : "r"(addr));
}
__device__ __forceinline__ void mma16816(float* d, const unsigned* a, const unsigned* b) {
    asm volatile(
        "mma.sync.aligned.m16n8k16.row.col.f32.bf16.bf16.f32 "
        "{%0,%1,%2,%3}, {%4,%5,%6,%7}, {%8,%9}, {%0,%1,%2,%3};"
        : "+f"(d[0]), "+f"(d[1]), "+f"(d[2]), "+f"(d[3])
        : "r"(a[0]), "r"(a[1]), "r"(a[2]), "r"(a[3]), "r"(b[0]), "r"(b[1]));
}

// ---------------- embed + deg-zero + weight-image build ----------------
__global__ void embed_kernel(const float* __restrict__ nodes,
                             const float* __restrict__ We,
                             const float* __restrict__ be,
                             const float* __restrict__ mlpW) {
    __shared__ float Wsh[NF * LAT];
    __shared__ float bsh[LAT];
    int tid = threadIdx.x;
    int gid = blockIdx.x * 256 + tid;
    if (gid < NN) { g_degs[gid] = 0.f; g_degr[gid] = 0.f; }
    if (gid < 6 * LAT * LAT) {
        int sl = gid >> 14;
        int rem = gid & 16383;
        int k = rem >> 7;
        int j = rem & 127;
        float w = mlpW[(size_t)sl * LAT * LAT + k * LAT + j];
        __nv_bfloat16 h = __float2bfloat16(w);
        __nv_bfloat16 l = __float2bfloat16(w - __bfloat162float(h));
        size_t off = (size_t)sl * 2 * IMG_BYTES + ((size_t)k * PA + j) * 2;
        *(__nv_bfloat16*)(g_wimg + off) = h;
        *(__nv_bfloat16*)(g_wimg + off + IMG_BYTES) = l;
    }
    for (int i = tid; i < NF * LAT; i += 256) Wsh[i] = We[i];
    if (tid < LAT) bsh[tid] = be[tid];
    __syncthreads();
    int warp = tid >> 5, lane = tid & 31;
    int n = blockIdx.x * 8 + warp;
    if (n >= NN) return;
    float t = (lane < NF) ? nodes[n * NF + lane] : 0.f;
    float f[NF];
#pragma unroll
    for (int k = 0; k < NF; k++) f[k] = __shfl_sync(0xFFFFFFFFu, t, k);
    int c0 = lane * 4;
    float4 o = make_float4(bsh[c0], bsh[c0 + 1], bsh[c0 + 2], bsh[c0 + 3]);
#pragma unroll
    for (int k = 0; k < NF; k++) {
        float4 w = *(const float4*)(Wsh + k * LAT + c0);
        o.x = fmaf(f[k], w.x, o.x);
        o.y = fmaf(f[k], w.y, o.y);
        o.z = fmaf(f[k], w.z, o.z);
        o.w = fmaf(f[k], w.w, o.w);
    }
    ((float4*)g_h)[n * 32 + lane] = o;
    store_h_image(n, lane, o);
}

__global__ void deg_kernel(const int* __restrict__ s, const int* __restrict__ r) {
    int e = blockIdx.x * blockDim.x + threadIdx.x;
    if (e < NE) {
        atomicAdd(&g_degs[s[e]], 1.f);
        atomicAdd(&g_degr[r[e]], 1.f);
    }
}

// ---------------- scans ----------------
__global__ void scan1_kernel() {
    int i = blockIdx.x * 1024 + threadIdx.x;
    int v = 0;
    if (i < NN) {
        float ds = g_degs[i], dr = g_degr[i];
        g_invs[i] = rsqrtf(fmaxf(ds, 1.f));
        g_invr[i] = rsqrtf(fmaxf(dr, 1.f));
        v = (int)dr;
    }
#pragma unroll
    for (int o = 16; o; o >>= 1) v += __shfl_xor_sync(0xFFFFFFFFu, v, o);
    __shared__ int ws[32];
    int lane = threadIdx.x & 31, warp = threadIdx.x >> 5;
    if (lane == 0) ws[warp] = v;
    __syncthreads();
    if (warp == 0) {
        int t = ws[lane];
#pragma unroll
        for (int o = 16; o; o >>= 1) t += __shfl_xor_sync(0xFFFFFFFFu, t, o);
        if (lane == 0) g_bsum[blockIdx.x] = t;
    }
}

// block-local scan + per-block base (folds old scan2) -> g_off, g_cursor
__global__ void scan3_kernel() {
    __shared__ int part[2];
    __shared__ int ws[32];
    int t = threadIdx.x;
    // base = sum of g_bsum[0 .. bid-1] (bid <= 48 < 64)
    if (t < 64) {
        int v = (t < (int)blockIdx.x) ? g_bsum[t] : 0;
#pragma unroll
        for (int o = 16; o; o >>= 1) v += __shfl_xor_sync(0xFFFFFFFFu, v, o);
        if ((t & 31) == 0) part[t >> 5] = v;
    }
    __syncthreads();
    int base = part[0] + part[1];

    int i = blockIdx.x * 1024 + t;
    int lane = t & 31, warp = t >> 5;
    int v = (i < NN) ? (int)g_degr[i] : 0;
    int x = v;
#pragma unroll
    for (int o = 1; o < 32; o <<= 1) {
        int y = __shfl_up_sync(0xFFFFFFFFu, x, o);
        if (lane >= o) x += y;
    }
    if (lane == 31) ws[warp] = x;
    __syncthreads();
    if (warp == 0) {
        int tt = ws[lane];
        int xx = tt;
#pragma unroll
        for (int o = 1; o < 32; o <<= 1) {
            int y = __shfl_up_sync(0xFFFFFFFFu, xx, o);
            if (lane >= o) xx += y;
        }
        ws[lane] = xx - tt;
    }
    __syncthreads();
    int ex = x - v + ws[warp] + base;
    if (i < NN) { g_off[i] = ex; g_cursor[i] = ex; }
    if (i == 0) g_off[NN] = NE;
}

__global__ void place_kernel(const int* __restrict__ snd, const int* __restrict__ rcv) {
    int e = blockIdx.x * blockDim.x + threadIdx.x;
    if (e < NE) {
        int pos = atomicAdd(&g_cursor[rcv[e]], 1);
        g_esrc[pos] = snd[e];
    }
}

// ---------------- mma.sync bf16x3 fused 2-layer MLP (persistent, pipelined) ----------------
struct Frag { unsigned ah[2][4], al[2][4], wh[2][4], wl[2][4]; };

__device__ __forceinline__ void load_frag(Frag& f, unsigned sAh, unsigned sAl,
                                          unsigned sWh, unsigned sWl,
                                          unsigned a_off, unsigned b_off) {
    ldsm4(f.ah[0], sAh + a_off);
    ldsm4(f.ah[1], sAh + a_off + 16 * PA * 2);
    ldsm4t(f.wh[0], sWh + b_off);
    ldsm4t(f.wh[1], sWh + b_off + 32);
    ldsm4(f.al[0], sAl + a_off);
    ldsm4(f.al[1], sAl + a_off + 16 * PA * 2);
    ldsm4t(f.wl[0], sWl + b_off);
    ldsm4t(f.wl[1], sWl + b_off + 32);
}

__device__ __forceinline__ void mma_layer(unsigned sAh, unsigned sAl, unsigned sWh,
                                          unsigned sWl, float acc[2][4][4],
                                          int lane, int row_w, int col_w) {
    int lr = lane & 15, lc = lane >> 4;
    int br = lane & 7, bseg = lane >> 3;
    unsigned a_base = ((row_w + lr) * PA + lc * 8) * 2;
    unsigned b_base = (((bseg & 1) * 8 + br) * PA + col_w + (bseg >> 1) * 8) * 2;

    Frag fr[2];
    load_frag(fr[0], sAh, sAl, sWh, sWl, a_base, b_base);
#pragma unroll
    for (int kt = 0; kt < 8; kt++) {
        int cur = kt & 1, nxt = cur ^ 1;
        if (kt < 7)
            load_frag(fr[nxt], sAh, sAl, sWh, sWl, a_base + (kt + 1) * 32,
                      b_base + (kt + 1) * (16 * PA * 2));
        Frag& f = fr[cur];
#pragma unroll
        for (int mt = 0; mt < 2; mt++)
#pragma unroll
            for (int nt = 0; nt < 4; nt++) {
                const unsigned* bh = &f.wh[nt >> 1][(nt & 1) * 2];
                const unsigned* bl = &f.wl[nt >> 1][(nt & 1) * 2];
                mma16816(acc[mt][nt], f.ah[mt], bh);
                mma16816(acc[mt][nt], f.ah[mt], bl);
                mma16816(acc[mt][nt], f.al[mt], bh);
            }
    }
}

__global__ void __launch_bounds__(512)
mlp_mma_kernel(int step, const float* __restrict__ b1g, const float* __restrict__ b2g) {
    extern __shared__ unsigned char smem[];
    unsigned sb = smem_u32(smem);
    int tid = threadIdx.x, wid = tid >> 5, lane = tid & 31;
    int row_w = (wid >> 2) * 32;
    int col_w = (wid & 3) * 32;
    float* b1s = (float*)(smem + SM_BIAS);
    float* b2s = (float*)(smem + SM_BIAS + 512);
    int qr = lane >> 2;
    int qc = (lane & 3) * 2;

    // weights + biases: once per persistent CTA
    {
        const unsigned char* srcW = g_wimg + (size_t)step * 4 * IMG_BYTES;
        for (int i = tid; i < 4 * IMG_BYTES / 16; i += 512)
            cpasync16(sb + SM_W1H + i * 16, srcW + i * 16);
        if (tid < 128) b1s[tid] = b1g[tid];
        else if (tid < 256) b2s[tid - 128] = b2g[tid - 128];
    }
    // first A tile
    {
        const unsigned char* srcA = g_ahi + (size_t)blockIdx.x * IMG_BYTES;
        const unsigned char* srcL = g_alo + (size_t)blockIdx.x * IMG_BYTES;
        for (int i = tid; i < IMG_BYTES / 16; i += 512) {
            cpasync16(sb + SM_A_HI + i * 16, srcA + i * 16);
            cpasync16(sb + SM_A_LO + i * 16, srcL + i * 16);
        }
        asm volatile("cp.async.commit_group;" ::: "memory");
    }

    for (int t = blockIdx.x; t < TILES; t += NPERS) {
        asm volatile("cp.async.wait_group 0;" ::: "memory");
        __syncthreads();

        float acc[2][4][4];
#pragma unroll
        for (int mt = 0; mt < 2; mt++)
#pragma unroll
            for (int nt = 0; nt < 4; nt++)
#pragma unroll
                for (int q = 0; q < 4; q++) acc[mt][nt][q] = 0.f;

        // ---- layer 1 ----
        mma_layer(sb + SM_A_HI, sb + SM_A_LO, sb + SM_W1H, sb + SM_W1L, acc,
                  lane, row_w, col_w);
        __syncthreads();  // all A reads done before overwrite

        // epilogue 1: relu + bias, re-split to bf16 hi/lo back into A images
#pragma unroll
        for (int mt = 0; mt < 2; mt++)
#pragma unroll
            for (int nt = 0; nt < 4; nt++) {
                int r0 = row_w + mt * 16 + qr;
                int c = col_w + nt * 8 + qc;
                float v00 = fmaxf(acc[mt][nt][0] + b1s[c], 0.f);
                float v01 = fmaxf(acc[mt][nt][1] + b1s[c + 1], 0.f);
                float v10 = fmaxf(acc[mt][nt][2] + b1s[c], 0.f);
                float v11 = fmaxf(acc[mt][nt][3] + b1s[c + 1], 0.f);
                unsigned h, l;
                split_pair(v00, v01, h, l);
                *(unsigned*)(smem + SM_A_HI + (r0 * PA + c) * 2) = h;
                *(unsigned*)(smem + SM_A_LO + (r0 * PA + c) * 2) = l;
                split_pair(v10, v11, h, l);
                *(unsigned*)(smem + SM_A_HI + ((r0 + 8) * PA + c) * 2) = h;
                *(unsigned*)(smem + SM_A_LO + ((r0 + 8) * PA + c) * 2) = l;
#pragma unroll
                for (int q = 0; q < 4; q++) acc[mt][nt][q] = 0.f;
            }
        __syncthreads();

        // ---- layer 2 ----
        mma_layer(sb + SM_A_HI, sb + SM_A_LO, sb + SM_W2H, sb + SM_W2L, acc,
                  lane, row_w, col_w);
        __syncthreads();  // all intermediate reads done

        // prefetch next tile's A while doing epilogue 2
        int tn = t + NPERS;
        if (tn < TILES) {
            const unsigned char* srcA = g_ahi + (size_t)tn * IMG_BYTES;
            const unsigned char* srcL = g_alo + (size_t)tn * IMG_BYTES;
            for (int i = tid; i < IMG_BYTES / 16; i += 512) {
                cpasync16(sb + SM_A_HI + i * 16, srcA + i * 16);
                cpasync16(sb + SM_A_LO + i * 16, srcL + i * 16);
            }
            asm volatile("cp.async.commit_group;" ::: "memory");
        }

        // epilogue 2: relu + bias, * invs, store fp32 to g_x
#pragma unroll
        for (int mt = 0; mt < 2; mt++) {
#pragma unroll
            for (int half = 0; half < 2; half++) {
                int r = row_w + mt * 16 + half * 8 + qr;
                int node = t * 128 + r;
                if (node < NN) {
                    float sc = g_invs[node];
#pragma unroll
                    for (int nt = 0; nt < 4; nt++) {
                        int c = col_w + nt * 8 + qc;
                        float2 o;
                        o.x = fmaxf(acc[mt][nt][2 * half] + b2s[c], 0.f) * sc;
                        o.y = fmaxf(acc[mt][nt][2 * half + 1] + b2s[c + 1], 0.f) * sc;
                        *(float2*)(g_x + (size_t)node * LAT + c) = o;
                    }
                }
            }
        }
    }
}

// ---------------- fused CSR-gather + skip + inv_sqrt_r + layernorm ----------------
__global__ void gather_ln_kernel(const float* __restrict__ lns,
                                 const float* __restrict__ lnb, int write_img) {
    int gw = (blockIdx.x * blockDim.x + threadIdx.x) >> 5;
    if (gw >= NN) return;
    int lane = threadIdx.x & 31;
    int n = gw;
    int beg = g_off[n], end = g_off[n + 1];

    const float4* X = (const float4*)g_x;
    float4 acc = make_float4(0.f, 0.f, 0.f, 0.f);
    int i = beg;
    for (; i + 3 < end; i += 4) {
        int s0 = g_esrc[i], s1 = g_esrc[i + 1], s2 = g_esrc[i + 2], s3 = g_esrc[i + 3];
        float4 v0 = __ldg(&X[s0 * 32 + lane]);
        float4 v1 = __ldg(&X[s1 * 32 + lane]);
        float4 v2 = __ldg(&X[s2 * 32 + lane]);
        float4 v3 = __ldg(&X[s3 * 32 + lane]);
        acc.x += v0.x + v1.x + v2.x + v3.x;
        acc.y += v0.y + v1.y + v2.y + v3.y;
        acc.z += v0.z + v1.z + v2.z + v3.z;
        acc.w += v0.w + v1.w + v2.w + v3.w;
    }
    for (; i < end; i++) {
        int s = g_esrc[i];
        float4 v = __ldg(&X[s * 32 + lane]);
        acc.x += v.x; acc.y += v.y; acc.z += v.z; acc.w += v.w;
    }

    float ir = g_invr[n];
    float4 h4 = ((const float4*)g_h)[n * 32 + lane];
    float4 v;
    v.x = h4.x + acc.x * ir;
    v.y = h4.y + acc.y * ir;
    v.z = h4.z + acc.z * ir;
    v.w = h4.w + acc.w * ir;

    float s1 = v.x + v.y + v.z + v.w;
    float s2 = v.x * v.x + v.y * v.y + v.z * v.z + v.w * v.w;
#pragma unroll
    for (int o = 16; o; o >>= 1) {
        s1 += __shfl_xor_sync(0xFFFFFFFFu, s1, o);
        s2 += __shfl_xor_sync(0xFFFFFFFFu, s2, o);
    }
    float mean = s1 * (1.f / 128.f);
    float var = s2 * (1.f / 128.f) - mean * mean;
    float rs = rsqrtf(var + 1e-6f);

    float4 g4 = __ldg(&((const float4*)lns)[lane]);
    float4 b4 = __ldg(&((const float4*)lnb)[lane]);
    float4 o;
    o.x = (v.x - mean) * rs * g4.x + b4.x;
    o.y = (v.y - mean) * rs * g4.y + b4.y;
    o.z = (v.z - mean) * rs * g4.z + b4.z;
    o.w = (v.w - mean) * rs * g4.w + b4.w;
    ((float4*)g_h)[n * 32 + lane] = o;
    if (write_img) store_h_image(n, lane, o);
}

// ---------------- decoder ----------------
__global__ void dec_kernel(const float* __restrict__ Wd, const float* __restrict__ bd,
                           float* __restrict__ out) {
    __shared__ float Wds[LAT * NF];
    int tid = threadIdx.x;
    for (int i = tid; i < LAT * NF; i += 256) Wds[i] = Wd[i];
    __syncthreads();
    int warp = tid >> 5, lane = tid & 31;
    int n = blockIdx.x * 8 + warp;
    if (n >= NN) return;
    float4 hv = ((const float4*)g_h)[n * 32 + lane];
#pragma unroll
    for (int f = 0; f < NF; f++) {
        float p = hv.x * Wds[(lane * 4 + 0) * NF + f] +
                  hv.y * Wds[(lane * 4 + 1) * NF + f] +
                  hv.z * Wds[(lane * 4 + 2) * NF + f] +
                  hv.w * Wds[(lane * 4 + 3) * NF + f];
#pragma unroll
        for (int o = 16; o; o >>= 1) p += __shfl_xor_sync(0xFFFFFFFFu, p, o);
        if (lane == 0) out[n * NF + f] = p + bd[f];
    }
}

// ---------------- launch ----------------
extern "C" void kernel_launch(void* const* d_in, const int* in_sizes, int n_in,
                              void* d_out, int out_size) {
    const float* nodes    = (const float*)d_in[0];
    const int*   senders  = (const int*)d_in[1];
    const int*   receivers= (const int*)d_in[2];
    const float* W_embed  = (const float*)d_in[3];
    const float* b_embed  = (const float*)d_in[4];
    const float* mlp_W    = (const float*)d_in[5];
    const float* mlp_b    = (const float*)d_in[6];
    const float* ln_scale = (const float*)d_in[7];
    const float* ln_bias  = (const float*)d_in[8];
    const float* W_dec    = (const float*)d_in[9];
    const float* b_dec    = (const float*)d_in[10];
    float* out = (float*)d_out;

    cudaFuncSetAttribute((const void*)mlp_mma_kernel,
                         cudaFuncAttributeMaxDynamicSharedMemorySize, SM_TOTAL);

    const int NB_SCAN = (NN + 1023) / 1024;  // 49

    // order: mlp step0 is the 4th launch (ncu capture slot)
    embed_kernel<<<(NN + 7) / 8, 256>>>(nodes, W_embed, b_embed, mlp_W);  // 1
    deg_kernel<<<(NE + 255) / 256, 256>>>(senders, receivers);            // 2
    scan1_kernel<<<NB_SCAN, 1024>>>();                                    // 3

    for (int s = 0; s < 3; s++) {
        const float* b1 = mlp_b + (size_t)(s * 2 + 0) * LAT;
        const float* b2 = mlp_b + (size_t)(s * 2 + 1) * LAT;
        mlp_mma_kernel<<<NPERS, 512, SM_TOTAL>>>(s, b1, b2);              // 4 on s=0
        if (s == 0) {
            scan3_kernel<<<NB_SCAN, 1024>>>();
            place_kernel<<<(NE + 255) / 256, 256>>>(senders, receivers);
        }
        gather_ln_kernel<<<(NN + 7) / 8, 256>>>(ln_scale + s * LAT, ln_bias + s * LAT,
                                                s < 2 ? 1 : 0);
    }

    dec_kernel<<<(NN + 7) / 8, 256>>>(W_dec, b_dec, out);
}

// round 8
// speedup vs baseline: 3.8171x; 1.1824x over previous
#include <cuda_runtime.h>
#include <cuda_bf16.h>
#include <cuda_fp16.h>

#define NN 50000
#define NE 600000
#define LAT 128
#define NF 7
#define TILES 391          // ceil(NN/128)
#define NPERS 131          // persistent mlp grid (131*3 >= 391, single wave)
#define PA 136             // fp16 elems per image row (272B: conflict-free ldmatrix)
#define IMG_BYTES (128 * PA * 2)   // 34816

// smem layout (bytes) for mlp kernel
#define SM_A    0
#define SM_W1H  (SM_A + IMG_BYTES)
#define SM_W1L  (SM_W1H + IMG_BYTES)
#define SM_W2H  (SM_W1L + IMG_BYTES)
#define SM_W2L  (SM_W2H + IMG_BYTES)
#define SM_BIAS (SM_W2L + IMG_BYTES)       // 174080
#define SM_TOTAL (SM_BIAS + 1024)          // 175104

// ---------------- scratch ----------------
__device__ float g_h[NN * LAT];
__device__ float g_x[NN * LAT];
__device__ float g_degs[NN];
__device__ float g_degr[NN];
__device__ float g_invs[NN];
__device__ float g_invr[NN];
__device__ int   g_off[NN + 1];
__device__ int   g_cursor[NN];
__device__ int   g_esrc[NE];
__device__ int   g_bsum[64];
__device__ unsigned char g_aimg[(size_t)TILES * IMG_BYTES];   // fp16 A images
__device__ unsigned char g_wimg[6 * 2 * IMG_BYTES];           // [step*2+layer][hi|lo] fp16

// ---------------- helpers ----------------
__device__ __forceinline__ unsigned smem_u32(const void* p) {
    unsigned a;
    asm("{ .reg .u64 t; cvta.to.shared.u64 t, %1; cvt.u32.u64 %0, t; }"
        : "=r"(a) : "l"(p));
    return a;
}
__device__ __forceinline__ void cpasync16(unsigned s, const void* g) {
    asm volatile("cp.async.cg.shared.global [%0], [%1], 16;" :: "r"(s), "l"(g));
}
__device__ __forceinline__ unsigned pack_h2(float v0, float v1) {
    __half2 h = __halves2half2(__float2half_rn(v0), __float2half_rn(v1));
    return *reinterpret_cast<unsigned*>(&h);
}
// write node n's 4 columns (k0=lane*4) into the fp16 tile image
__device__ __forceinline__ void store_h_image(int n, int lane, float4 v) {
    int tile = n >> 7, r = n & 127;
    size_t off = (size_t)tile * IMG_BYTES + ((size_t)r * PA + lane * 4) * 2;
    *(uint2*)(g_aimg + off) = make_uint2(pack_h2(v.x, v.y), pack_h2(v.z, v.w));
}
__device__ __forceinline__ void ldsm4(unsigned* r, unsigned addr) {
    asm volatile("ldmatrix.sync.aligned.m8n8.x4.shared.b16 {%0,%1,%2,%3}, [%4];"
                 : "=r"(r[0]), "=r"(r[1]), "=r"(r[2]), "=r"(r[3]) : "r"(addr));
}
__device__ __forceinline__ void ldsm4t(unsigned* r, unsigned addr) {
    asm volatile("ldmatrix.sync.aligned.m8n8.x4.trans.shared.b16 {%0,%1,%2,%3}, [%4];"
                 : "=r"(r[0]), "=r"(r[1]), "=r"(r[2]), "=r"(r[3]) : "r"(addr));
}
__device__ __forceinline__ void mma16816(float* d, const unsigned* a, const unsigned* b) {
    asm volatile(
        "mma.sync.aligned.m16n8k16.row.col.f32.f16.f16.f32 "
        "{%0,%1,%2,%3}, {%4,%5,%6,%7}, {%8,%9}, {%0,%1,%2,%3};"
        : "+f"(d[0]), "+f"(d[1]), "+f"(d[2]), "+f"(d[3])
        : "r"(a[0]), "r"(a[1]), "r"(a[2]), "r"(a[3]), "r"(b[0]), "r"(b[1]));
}

// ---------------- embed + deg-zero + weight-image build ----------------
__global__ void embed_kernel(const float* __restrict__ nodes,
                             const float* __restrict__ We,
                             const float* __restrict__ be,
                             const float* __restrict__ mlpW) {
    __shared__ float Wsh[NF * LAT];
    __shared__ float bsh[LAT];
    int tid = threadIdx.x;
    int gid = blockIdx.x * 256 + tid;
    if (gid < NN) { g_degs[gid] = 0.f; g_degr[gid] = 0.f; }
    // weight images: 6 layers x [k][j], fp16 hi/lo split
    if (gid < 6 * LAT * LAT) {
        int sl = gid >> 14;
        int rem = gid & 16383;
        int k = rem >> 7;
        int j = rem & 127;
        float w = mlpW[(size_t)sl * LAT * LAT + k * LAT + j];
        __half h = __float2half_rn(w);
        __half l = __float2half_rn(w - __half2float(h));
        size_t off = (size_t)sl * 2 * IMG_BYTES + ((size_t)k * PA + j) * 2;
        *(__half*)(g_wimg + off) = h;
        *(__half*)(g_wimg + off + IMG_BYTES) = l;
    }
    for (int i = tid; i < NF * LAT; i += 256) Wsh[i] = We[i];
    if (tid < LAT) bsh[tid] = be[tid];
    __syncthreads();
    int warp = tid >> 5, lane = tid & 31;
    int n = blockIdx.x * 8 + warp;
    if (n >= NN) return;
    float t = (lane < NF) ? nodes[n * NF + lane] : 0.f;
    float f[NF];
#pragma unroll
    for (int k = 0; k < NF; k++) f[k] = __shfl_sync(0xFFFFFFFFu, t, k);
    int c0 = lane * 4;
    float4 o = make_float4(bsh[c0], bsh[c0 + 1], bsh[c0 + 2], bsh[c0 + 3]);
#pragma unroll
    for (int k = 0; k < NF; k++) {
        float4 w = *(const float4*)(Wsh + k * LAT + c0);
        o.x = fmaf(f[k], w.x, o.x);
        o.y = fmaf(f[k], w.y, o.y);
        o.z = fmaf(f[k], w.z, o.z);
        o.w = fmaf(f[k], w.w, o.w);
    }
    ((float4*)g_h)[n * 32 + lane] = o;
    store_h_image(n, lane, o);
}

__global__ void deg_kernel(const int* __restrict__ s, const int* __restrict__ r) {
    int e = blockIdx.x * blockDim.x + threadIdx.x;
    if (e < NE) {
        atomicAdd(&g_degs[s[e]], 1.f);
        atomicAdd(&g_degr[r[e]], 1.f);
    }
}

// ---------------- scans ----------------
__global__ void scan1_kernel() {
    int i = blockIdx.x * 1024 + threadIdx.x;
    int v = 0;
    if (i < NN) {
        float ds = g_degs[i], dr = g_degr[i];
        g_invs[i] = rsqrtf(fmaxf(ds, 1.f));
        g_invr[i] = rsqrtf(fmaxf(dr, 1.f));
        v = (int)dr;
    }
#pragma unroll
    for (int o = 16; o; o >>= 1) v += __shfl_xor_sync(0xFFFFFFFFu, v, o);
    __shared__ int ws[32];
    int lane = threadIdx.x & 31, warp = threadIdx.x >> 5;
    if (lane == 0) ws[warp] = v;
    __syncthreads();
    if (warp == 0) {
        int t = ws[lane];
#pragma unroll
        for (int o = 16; o; o >>= 1) t += __shfl_xor_sync(0xFFFFFFFFu, t, o);
        if (lane == 0) g_bsum[blockIdx.x] = t;
    }
}

// block-local scan + per-block base -> g_off, g_cursor
__global__ void scan3_kernel() {
    __shared__ int part[2];
    __shared__ int ws[32];
    int t = threadIdx.x;
    if (t < 64) {
        int v = (t < (int)blockIdx.x) ? g_bsum[t] : 0;
#pragma unroll
        for (int o = 16; o; o >>= 1) v += __shfl_xor_sync(0xFFFFFFFFu, v, o);
        if ((t & 31) == 0) part[t >> 5] = v;
    }
    __syncthreads();
    int base = part[0] + part[1];

    int i = blockIdx.x * 1024 + t;
    int lane = t & 31, warp = t >> 5;
    int v = (i < NN) ? (int)g_degr[i] : 0;
    int x = v;
#pragma unroll
    for (int o = 1; o < 32; o <<= 1) {
        int y = __shfl_up_sync(0xFFFFFFFFu, x, o);
        if (lane >= o) x += y;
    }
    if (lane == 31) ws[warp] = x;
    __syncthreads();
    if (warp == 0) {
        int tt = ws[lane];
        int xx = tt;
#pragma unroll
        for (int o = 1; o < 32; o <<= 1) {
            int y = __shfl_up_sync(0xFFFFFFFFu, xx, o);
            if (lane >= o) xx += y;
        }
        ws[lane] = xx - tt;
    }
    __syncthreads();
    int ex = x - v + ws[warp] + base;
    if (i < NN) { g_off[i] = ex; g_cursor[i] = ex; }
    if (i == 0) g_off[NN] = NE;
}

__global__ void place_kernel(const int* __restrict__ snd, const int* __restrict__ rcv) {
    int e = blockIdx.x * blockDim.x + threadIdx.x;
    if (e < NE) {
        int pos = atomicAdd(&g_cursor[rcv[e]], 1);
        g_esrc[pos] = snd[e];
    }
}

// ---------------- mma.sync fp16x2 fused 2-layer MLP (persistent) ----------------
// per k-tile per warp: 2 ldsm A, 4 ldsm W, 16 MMA:  acc += A*Whi + A*Wlo
__device__ __forceinline__ void mma_layer(unsigned sA, unsigned sWh, unsigned sWl,
                                          float acc[2][4][4],
                                          int lane, int row_w, int col_w) {
    int lr = lane & 15, lc = lane >> 4;
    int br = lane & 7, bseg = lane >> 3;
    unsigned a_base = ((row_w + lr) * PA + lc * 8) * 2;
    unsigned b_base = (((bseg & 1) * 8 + br) * PA + col_w + (bseg >> 1) * 8) * 2;

#pragma unroll
    for (int kt = 0; kt < 8; kt++) {
        unsigned a_off = a_base + kt * 32;
        unsigned b_off = b_base + kt * (16 * PA * 2);
        unsigned a[2][4], wh[2][4], wl[2][4];
        ldsm4(a[0], sA + a_off);
        ldsm4(a[1], sA + a_off + 16 * PA * 2);
        ldsm4t(wh[0], sWh + b_off);
        ldsm4t(wh[1], sWh + b_off + 32);
        ldsm4t(wl[0], sWl + b_off);
        ldsm4t(wl[1], sWl + b_off + 32);
#pragma unroll
        for (int mt = 0; mt < 2; mt++)
#pragma unroll
            for (int nt = 0; nt < 4; nt++) {
                const unsigned* bh = &wh[nt >> 1][(nt & 1) * 2];
                const unsigned* bl = &wl[nt >> 1][(nt & 1) * 2];
                mma16816(acc[mt][nt], a[mt], bh);
                mma16816(acc[mt][nt], a[mt], bl);
            }
    }
}

__global__ void __launch_bounds__(512)
mlp_mma_kernel(int step, const float* __restrict__ b1g, const float* __restrict__ b2g) {
    extern __shared__ unsigned char smem[];
    unsigned sb = smem_u32(smem);
    int tid = threadIdx.x, wid = tid >> 5, lane = tid & 31;
    int row_w = (wid >> 2) * 32;
    int col_w = (wid & 3) * 32;
    float* b1s = (float*)(smem + SM_BIAS);
    float* b2s = (float*)(smem + SM_BIAS + 512);
    int qr = lane >> 2;
    int qc = (lane & 3) * 2;

    // weights + biases: once per persistent CTA
    {
        const unsigned char* srcW = g_wimg + (size_t)step * 4 * IMG_BYTES;
        for (int i = tid; i < 4 * IMG_BYTES / 16; i += 512)
            cpasync16(sb + SM_W1H + i * 16, srcW + i * 16);
        if (tid < 128) b1s[tid] = b1g[tid];
        else if (tid < 256) b2s[tid - 128] = b2g[tid - 128];
    }
    // first A tile
    {
        const unsigned char* srcA = g_aimg + (size_t)blockIdx.x * IMG_BYTES;
        for (int i = tid; i < IMG_BYTES / 16; i += 512)
            cpasync16(sb + SM_A + i * 16, srcA + i * 16);
        asm volatile("cp.async.commit_group;" ::: "memory");
    }

    for (int t = blockIdx.x; t < TILES; t += NPERS) {
        asm volatile("cp.async.wait_group 0;" ::: "memory");
        __syncthreads();

        float acc[2][4][4];
#pragma unroll
        for (int mt = 0; mt < 2; mt++)
#pragma unroll
            for (int nt = 0; nt < 4; nt++)
#pragma unroll
                for (int q = 0; q < 4; q++) acc[mt][nt][q] = 0.f;

        // ---- layer 1 ----
        mma_layer(sb + SM_A, sb + SM_W1H, sb + SM_W1L, acc, lane, row_w, col_w);
        __syncthreads();  // all A reads done before overwrite

        // epilogue 1: relu + bias, fp16 back into A image
#pragma unroll
        for (int mt = 0; mt < 2; mt++)
#pragma unroll
            for (int nt = 0; nt < 4; nt++) {
                int r0 = row_w + mt * 16 + qr;
                int c = col_w + nt * 8 + qc;
                float v00 = fmaxf(acc[mt][nt][0] + b1s[c], 0.f);
                float v01 = fmaxf(acc[mt][nt][1] + b1s[c + 1], 0.f);
                float v10 = fmaxf(acc[mt][nt][2] + b1s[c], 0.f);
                float v11 = fmaxf(acc[mt][nt][3] + b1s[c + 1], 0.f);
                *(unsigned*)(smem + SM_A + (r0 * PA + c) * 2) = pack_h2(v00, v01);
                *(unsigned*)(smem + SM_A + ((r0 + 8) * PA + c) * 2) = pack_h2(v10, v11);
#pragma unroll
                for (int q = 0; q < 4; q++) acc[mt][nt][q] = 0.f;
            }
        __syncthreads();

        // ---- layer 2 ----
        mma_layer(sb + SM_A, sb + SM_W2H, sb + SM_W2L, acc, lane, row_w, col_w);
        __syncthreads();  // all intermediate reads done

        // prefetch next tile's A during epilogue 2
        int tn = t + NPERS;
        if (tn < TILES) {
            const unsigned char* srcA = g_aimg + (size_t)tn * IMG_BYTES;
            for (int i = tid; i < IMG_BYTES / 16; i += 512)
                cpasync16(sb + SM_A + i * 16, srcA + i * 16);
            asm volatile("cp.async.commit_group;" ::: "memory");
        }

        // epilogue 2: relu + bias, * invs, store fp32 to g_x
#pragma unroll
        for (int mt = 0; mt < 2; mt++) {
#pragma unroll
            for (int half = 0; half < 2; half++) {
                int r = row_w + mt * 16 + half * 8 + qr;
                int node = t * 128 + r;
                if (node < NN) {
                    float sc = g_invs[node];
#pragma unroll
                    for (int nt = 0; nt < 4; nt++) {
                        int c = col_w + nt * 8 + qc;
                        float2 o;
                        o.x = fmaxf(acc[mt][nt][2 * half] + b2s[c], 0.f) * sc;
                        o.y = fmaxf(acc[mt][nt][2 * half + 1] + b2s[c + 1], 0.f) * sc;
                        *(float2*)(g_x + (size_t)node * LAT + c) = o;
                    }
                }
            }
        }
    }
}

// ---------------- fused CSR-gather + skip + inv_sqrt_r + layernorm ----------------
__global__ void gather_ln_kernel(const float* __restrict__ lns,
                                 const float* __restrict__ lnb, int write_img) {
    int gw = (blockIdx.x * blockDim.x + threadIdx.x) >> 5;
    if (gw >= NN) return;
    int lane = threadIdx.x & 31;
    int n = gw;
    int beg = g_off[n], end = g_off[n + 1];

    const float4* X = (const float4*)g_x;
    float4 acc = make_float4(0.f, 0.f, 0.f, 0.f);
    int i = beg;
    for (; i + 3 < end; i += 4) {
        int s0 = g_esrc[i], s1 = g_esrc[i + 1], s2 = g_esrc[i + 2], s3 = g_esrc[i + 3];
        float4 v0 = __ldg(&X[s0 * 32 + lane]);
        float4 v1 = __ldg(&X[s1 * 32 + lane]);
        float4 v2 = __ldg(&X[s2 * 32 + lane]);
        float4 v3 = __ldg(&X[s3 * 32 + lane]);
        acc.x += v0.x + v1.x + v2.x + v3.x;
        acc.y += v0.y + v1.y + v2.y + v3.y;
        acc.z += v0.z + v1.z + v2.z + v3.z;
        acc.w += v0.w + v1.w + v2.w + v3.w;
    }
    for (; i < end; i++) {
        int s = g_esrc[i];
        float4 v = __ldg(&X[s * 32 + lane]);
        acc.x += v.x; acc.y += v.y; acc.z += v.z; acc.w += v.w;
    }

    float ir = g_invr[n];
    float4 h4 = ((const float4*)g_h)[n * 32 + lane];
    float4 v;
    v.x = h4.x + acc.x * ir;
    v.y = h4.y + acc.y * ir;
    v.z = h4.z + acc.z * ir;
    v.w = h4.w + acc.w * ir;

    float s1 = v.x + v.y + v.z + v.w;
    float s2 = v.x * v.x + v.y * v.y + v.z * v.z + v.w * v.w;
#pragma unroll
    for (int o = 16; o; o >>= 1) {
        s1 += __shfl_xor_sync(0xFFFFFFFFu, s1, o);
        s2 += __shfl_xor_sync(0xFFFFFFFFu, s2, o);
    }
    float mean = s1 * (1.f / 128.f);
    float var = s2 * (1.f / 128.f) - mean * mean;
    float rs = rsqrtf(var + 1e-6f);

    float4 g4 = __ldg(&((const float4*)lns)[lane]);
    float4 b4 = __ldg(&((const float4*)lnb)[lane]);
    float4 o;
    o.x = (v.x - mean) * rs * g4.x + b4.x;
    o.y = (v.y - mean) * rs * g4.y + b4.y;
    o.z = (v.z - mean) * rs * g4.z + b4.z;
    o.w = (v.w - mean) * rs * g4.w + b4.w;
    ((float4*)g_h)[n * 32 + lane] = o;
    if (write_img) store_h_image(n, lane, o);
}

// ---------------- decoder ----------------
__global__ void dec_kernel(const float* __restrict__ Wd, const float* __restrict__ bd,
                           float* __restrict__ out) {
    __shared__ float Wds[LAT * NF];
    int tid = threadIdx.x;
    for (int i = tid; i < LAT * NF; i += 256) Wds[i] = Wd[i];
    __syncthreads();
    int warp = tid >> 5, lane = tid & 31;
    int n = blockIdx.x * 8 + warp;
    if (n >= NN) return;
    float4 hv = ((const float4*)g_h)[n * 32 + lane];
#pragma unroll
    for (int f = 0; f < NF; f++) {
        float p = hv.x * Wds[(lane * 4 + 0) * NF + f] +
                  hv.y * Wds[(lane * 4 + 1) * NF + f] +
                  hv.z * Wds[(lane * 4 + 2) * NF + f] +
                  hv.w * Wds[(lane * 4 + 3) * NF + f];
#pragma unroll
        for (int o = 16; o; o >>= 1) p += __shfl_xor_sync(0xFFFFFFFFu, p, o);
        if (lane == 0) out[n * NF + f] = p + bd[f];
    }
}

// ---------------- launch ----------------
extern "C" void kernel_launch(void* const* d_in, const int* in_sizes, int n_in,
                              void* d_out, int out_size) {
    const float* nodes    = (const float*)d_in[0];
    const int*   senders  = (const int*)d_in[1];
    const int*   receivers= (const int*)d_in[2];
    const float* W_embed  = (const float*)d_in[3];
    const float* b_embed  = (const float*)d_in[4];
    const float* mlp_W    = (const float*)d_in[5];
    const float* mlp_b    = (const float*)d_in[6];
    const float* ln_scale = (const float*)d_in[7];
    const float* ln_bias  = (const float*)d_in[8];
    const float* W_dec    = (const float*)d_in[9];
    const float* b_dec    = (const float*)d_in[10];
    float* out = (float*)d_out;

    cudaFuncSetAttribute((const void*)mlp_mma_kernel,
                         cudaFuncAttributeMaxDynamicSharedMemorySize, SM_TOTAL);

    const int NB_SCAN = (NN + 1023) / 1024;  // 49

    // order: mlp step0 is the 4th launch (ncu capture slot)
    embed_kernel<<<(NN + 7) / 8, 256>>>(nodes, W_embed, b_embed, mlp_W);  // 1
    deg_kernel<<<(NE + 255) / 256, 256>>>(senders, receivers);            // 2
    scan1_kernel<<<NB_SCAN, 1024>>>();                                    // 3

    for (int s = 0; s < 3; s++) {
        const float* b1 = mlp_b + (size_t)(s * 2 + 0) * LAT;
        const float* b2 = mlp_b + (size_t)(s * 2 + 1) * LAT;
        mlp_mma_kernel<<<NPERS, 512, SM_TOTAL>>>(s, b1, b2);              // 4 on s=0
        if (s == 0) {
            scan3_kernel<<<NB_SCAN, 1024>>>();
            place_kernel<<<(NE + 255) / 256, 256>>>(senders, receivers);
        }
        gather_ln_kernel<<<(NN + 7) / 8, 256>>>(ln_scale + s * LAT, ln_bias + s * LAT,
                                                s < 2 ? 1 : 0);
    }

    dec_kernel<<<(NN + 7) / 8, 256>>>(W_dec, b_dec, out);
}